// round 11
// baseline (speedup 1.0000x reference)
#include <cuda_runtime.h>
#include <math.h>
#include <stdint.h>

#define DIM   256
#define NH    8
#define HD    32
#define NTOK  98
#define BW    2048
#define TBL   507                 // (2*2-1)*(2*7-1)*(2*7-1)
#define M_TOT (BW*NTOK)           // 200704
#define QST   36                  // q/k/v smem row stride (4g+tg banks distinct, 16B-aligned)
#define SST   108                 // S smem row stride (12g+tg banks distinct)
#define MPAD  112                 // tokens padded to 7 x m16

// ---------------- device scratch (no allocations allowed) ----------------
__device__ float g_qkv[(size_t)BW * NTOK * 3 * DIM];   // 616 MB
__device__ float g_att[(size_t)BW * NTOK * DIM];       // 205 MB
__device__ float g_bt[TBL * NH];                       // 16*sigmoid(cpb) table
__device__ float g_bias768[3 * DIM];
__device__ float g_scale[NH];

// ---------------- setup: fused bias + per-head logit scale ----------------
__global__ void setup_small(const float* __restrict__ qb,
                            const float* __restrict__ vb,
                            const float* __restrict__ ls) {
    int t = threadIdx.x;                       // 768 threads
    float b;
    if (t < 256)       b = qb[t];
    else if (t < 512)  b = 0.f;
    else               b = vb[t - 512];
    g_bias768[t] = b;
    if (t < NH) g_scale[t] = expf(fminf(ls[t], 4.6051701860f)); // log(100)
}

// ---------------- CPB MLP: table -> relu -> w2 -> 16*sigmoid ----------------
__global__ void cpb_kernel(const float* __restrict__ w1, const float* __restrict__ b1,
                           const float* __restrict__ w2) {
    __shared__ float hid[512];
    int t = blockIdx.x;                        // 0..506
    int a = t / 169, rem = t % 169, b = rem / 13, c = rem % 13;
    const float eps = 1e-6f;
    float ga = (float)(a - 1) / (2.f - (1.f - eps)) * 8.f;
    float gb = (float)(b - 6) / (7.f - (1.f - eps)) * 8.f;
    float gc = (float)(c - 6) / (7.f - (1.f - eps)) * 8.f;
    const float il8 = 1.f / log2f(8.f);
    ga = copysignf(log2f(fabsf(ga) + 1.f) * il8, ga);
    gb = copysignf(log2f(fabsf(gb) + 1.f) * il8, gb);
    gc = copysignf(log2f(fabsf(gc) + 1.f) * il8, gc);
    int j = threadIdx.x;                       // 512 threads
    float hv = ga * w1[j * 3 + 0] + gb * w1[j * 3 + 1] + gc * w1[j * 3 + 2] + b1[j];
    hid[j] = fmaxf(hv, 0.f);
    __syncthreads();
    if (j < NH) {
        float acc = 0.f;
        for (int q = 0; q < 512; q++) acc += hid[q] * w2[j * 512 + q];
        g_bt[t * NH + j] = 16.f / (1.f + expf(-acc));
    }
}

// ---------------- tf32 helpers ----------------
__device__ __forceinline__ uint32_t f2tf(float x) {
    uint32_t u;
    asm("cvt.rna.tf32.f32 %0, %1;" : "=r"(u) : "f"(x));
    return u;
}

__device__ __forceinline__ uint32_t smem_u32(const void* p) {
    uint32_t a;
    asm("{ .reg .u64 t; cvta.to.shared.u64 t, %1; cvt.u32.u64 %0, t; }"
        : "=r"(a) : "l"(p));
    return a;
}

__device__ __forceinline__ void mma_tf32(float* d, const uint32_t* a,
                                         const uint32_t* b, const float* c) {
    asm volatile(
        "mma.sync.aligned.m16n8k8.row.col.f32.tf32.tf32.f32 "
        "{%0,%1,%2,%3}, {%4,%5,%6,%7}, {%8,%9}, {%10,%11,%12,%13};\n"
        : "=f"(d[0]), "=f"(d[1]), "=f"(d[2]), "=f"(d[3])
        : "r"(a[0]), "r"(a[1]), "r"(a[2]), "r"(a[3]),
          "r"(b[0]), "r"(b[1]),
          "f"(c[0]), "f"(c[1]), "f"(c[2]), "f"(c[3]));
}

#define CP16(dst, src) \
    asm volatile("cp.async.cg.shared.global [%0], [%1], 16;" :: "r"(dst), "l"(src))
#define CP_COMMIT() asm volatile("cp.async.commit_group;" ::: "memory")
#define CP_WAIT1()  asm volatile("cp.async.wait_group 1;" ::: "memory")
#define CP_WAIT0()  asm volatile("cp.async.wait_group 0;" ::: "memory")

// ---------------- tf32 mma.sync GEMM, cp.async 3-stage ----------------
// C[M,Nout] = A[M,256] @ W[Nout,256]^T + bias.  Both A and W are K-major.
#define KCH    32
#define NCHUNK 8
#define RST    36                           // smem row stride (floats)
#define STG    (128 * RST)                  // one matrix stage (floats)
#define GEMM_SMEM (3 * 2 * STG * 4)         // 110592 bytes

__global__ __launch_bounds__(256) void gemm_tc(const float* __restrict__ A,
                                               const float* __restrict__ W,
                                               const float* __restrict__ bias,
                                               float* __restrict__ C, int Nout) {
    extern __shared__ float sm[];
    uint32_t sbase = smem_u32(sm);
    int tid = threadIdx.x;
    int wid = tid >> 5, lane = tid & 31;
    int g = lane >> 2, tg = lane & 3;
    int m0 = blockIdx.y * 128, n0 = blockIdx.x * 128;
    int wm = (wid & 3) * 32, wn = (wid >> 2) * 64;

    float acc[2][8][4] = {};

    int row0 = tid >> 3, seg = tid & 7;
    const float* Ap = A + (size_t)(m0 + row0) * 256 + seg * 4;
    const float* Wp = W + (size_t)(n0 + row0) * 256 + seg * 4;

    #define STAGE_CHUNK(cc) do {                                                  \
        int _st = (cc) % 3;                                                       \
        uint32_t _ab = sbase + (uint32_t)(_st * 2 * STG) * 4;                     \
        uint32_t _bb = _ab + (uint32_t)STG * 4;                                   \
        _Pragma("unroll")                                                         \
        for (int _j = 0; _j < 4; _j++) {                                          \
            int _r = row0 + _j * 32;                                              \
            uint32_t _o = (uint32_t)(_r * RST + seg * 4) * 4;                     \
            CP16(_ab + _o, Ap + (size_t)_j * 32 * 256 + (cc) * KCH);              \
            CP16(_bb + _o, Wp + (size_t)_j * 32 * 256 + (cc) * KCH);              \
        }                                                                         \
        CP_COMMIT();                                                              \
    } while (0)

    STAGE_CHUNK(0);
    STAGE_CHUNK(1);

    for (int c = 0; c < NCHUNK; c++) {
        if (c == NCHUNK - 1) CP_WAIT0(); else CP_WAIT1();
        __syncthreads();
        if (c + 2 < NCHUNK) STAGE_CHUNK(c + 2);

        const float* As = sm + (c % 3) * 2 * STG;
        const float* Bs = As + STG;
        #pragma unroll
        for (int kk = 0; kk < KCH; kk += 8) {
            uint32_t af[2][4];
            #pragma unroll
            for (int mi = 0; mi < 2; mi++) {
                int r = wm + mi * 16 + g;
                af[mi][0] = f2tf(As[r * RST + kk + tg]);
                af[mi][1] = f2tf(As[(r + 8) * RST + kk + tg]);
                af[mi][2] = f2tf(As[r * RST + kk + tg + 4]);
                af[mi][3] = f2tf(As[(r + 8) * RST + kk + tg + 4]);
            }
            uint32_t bf[8][2];
            #pragma unroll
            for (int ni = 0; ni < 8; ni++) {
                int n = wn + ni * 8 + g;
                bf[ni][0] = f2tf(Bs[n * RST + kk + tg]);
                bf[ni][1] = f2tf(Bs[n * RST + kk + tg + 4]);
            }
            #pragma unroll
            for (int mi = 0; mi < 2; mi++)
                #pragma unroll
                for (int ni = 0; ni < 8; ni++)
                    mma_tf32(acc[mi][ni], af[mi], bf[ni], acc[mi][ni]);
        }
        __syncthreads();
    }

    #pragma unroll
    for (int mi = 0; mi < 2; mi++) {
        #pragma unroll
        for (int ni = 0; ni < 8; ni++) {
            int row = m0 + wm + mi * 16 + g;
            int col = n0 + wn + ni * 8 + 2 * tg;
            float b0v = bias[col], b1v = bias[col + 1];
            *(float2*)&C[(size_t)row * Nout + col] =
                make_float2(acc[mi][ni][0] + b0v, acc[mi][ni][1] + b1v);
            *(float2*)&C[(size_t)(row + 8) * Nout + col] =
                make_float2(acc[mi][ni][2] + b0v, acc[mi][ni][3] + b1v);
        }
    }
}

// ---------------- fused per-(window,head) attention, tensor-core 3xTF32 ----
// smem floats: 3*112*36 + 112*108 + 507 = 24699  (98796 bytes)
#define ATTN_SMEM_FLOATS (3 * MPAD * QST + MPAD * SST + TBL)

__global__ __launch_bounds__(256, 2) void attn_kernel() {
    extern __shared__ float sm[];
    float* sq  = sm;
    float* sk  = sq + MPAD * QST;
    float* sv  = sk + MPAD * QST;
    float* sS  = sv + MPAD * QST;          // 112 x 108
    float* sbt = sS + MPAD * SST;          // 507
    int bx = blockIdx.x;
    int w = bx >> 3, h = bx & 7;
    int tid = threadIdx.x;
    int warp = tid >> 5, lane = tid & 31;
    int g = lane >> 2, tg = lane & 3;

    // fill q/k/v (rows 98..111 zero); float4 both sides (QST=36 -> 16B aligned)
    const float* base = g_qkv + (size_t)w * NTOK * 768 + h * HD;
    for (int e = tid; e < MPAD * 8; e += 256) {
        int n = e >> 3, d4 = (e & 7) * 4;
        float4 vq, vk, vv;
        if (n < NTOK) {
            const float* r = base + (size_t)n * 768;
            vq = *(const float4*)(r + d4);
            vk = *(const float4*)(r + 256 + d4);
            vv = *(const float4*)(r + 512 + d4);
        } else {
            vq = make_float4(0.f, 0.f, 0.f, 0.f); vk = vq; vv = vq;
        }
        *(float4*)&sq[n * QST + d4] = vq;
        *(float4*)&sk[n * QST + d4] = vk;
        *(float4*)&sv[n * QST + d4] = vv;
    }
    for (int e = tid; e < TBL; e += 256) sbt[e] = g_bt[e * NH + h];
    __syncthreads();

    // L2-normalize rows; fold cosine scale into q
    float scale = g_scale[h];
    if (tid < NTOK) {
        float nq = 0.f, nk = 0.f;
        for (int d = 0; d < HD; d++) {
            float a = sq[tid * QST + d]; nq += a * a;
            float b = sk[tid * QST + d]; nk += b * b;
        }
        float iq = scale / fmaxf(sqrtf(nq), 1e-12f);
        float ik = 1.f   / fmaxf(sqrtf(nk), 1e-12f);
        for (int d = 0; d < HD; d++) {
            sq[tid * QST + d] *= iq;
            sk[tid * QST + d] *= ik;
        }
    }
    __syncthreads();

    // ---- S = qn @ kn^T via 3xTF32 mma (warps 0..6, m16 tile each; 13 n8 tiles)
    if (warp < 7) {
        int mt = warp * 16;
        float acc[13][4] = {};
        #pragma unroll
        for (int ks = 0; ks < 4; ks++) {
            int kk = ks * 8;
            float a0 = sq[(mt + g) * QST + kk + tg];
            float a1 = sq[(mt + g + 8) * QST + kk + tg];
            float a2 = sq[(mt + g) * QST + kk + tg + 4];
            float a3 = sq[(mt + g + 8) * QST + kk + tg + 4];
            uint32_t ah[4] = {f2tf(a0), f2tf(a1), f2tf(a2), f2tf(a3)};
            uint32_t al[4] = {f2tf(a0 - __uint_as_float(ah[0])),
                              f2tf(a1 - __uint_as_float(ah[1])),
                              f2tf(a2 - __uint_as_float(ah[2])),
                              f2tf(a3 - __uint_as_float(ah[3]))};
            #pragma unroll
            for (int ni = 0; ni < 13; ni++) {
                float b0 = sk[(ni * 8 + g) * QST + kk + tg];
                float b1 = sk[(ni * 8 + g) * QST + kk + tg + 4];
                uint32_t bh[2] = {f2tf(b0), f2tf(b1)};
                uint32_t bl[2] = {f2tf(b0 - __uint_as_float(bh[0])),
                                  f2tf(b1 - __uint_as_float(bh[1]))};
                mma_tf32(acc[ni], ah, bh, acc[ni]);
                mma_tf32(acc[ni], ah, bl, acc[ni]);
                mma_tf32(acc[ni], al, bh, acc[ni]);
            }
        }
        // epilogue: + rpb into sS; invalid (pad) entries -> 0
        #pragma unroll
        for (int ni = 0; ni < 13; ni++) {
            #pragma unroll
            for (int half = 0; half < 2; half++) {
                int r = mt + g + half * 8;
                float v0 = acc[ni][half * 2], v1 = acc[ni][half * 2 + 1];
                int c0 = ni * 8 + 2 * tg;
                if (r < NTOK) {
                    int di = r / 49, ri = r % 49, hi = ri / 7, wi = ri % 7;
                    #pragma unroll
                    for (int u = 0; u < 2; u++) {
                        int c = c0 + u;
                        float v = u ? v1 : v0;
                        if (c < NTOK) {
                            int dj = c / 49, rj = c % 49, hj = rj / 7, wj = rj % 7;
                            int idx = (di - dj + 1) * 169 + (hi - hj + 6) * 13 + (wi - wj + 6);
                            sS[r * SST + c] = v + sbt[idx];
                        } else {
                            sS[r * SST + c] = 0.f;
                        }
                    }
                } else {
                    sS[r * SST + c0] = 0.f;
                    sS[r * SST + c0 + 1] = 0.f;
                }
            }
        }
    }
    __syncthreads();

    // warp-parallel row softmax (8 warps sweep 98 rows, cols < 98)
    for (int r = warp; r < NTOK; r += 8) {
        float* row = &sS[r * SST];
        float m = -1e30f;
        for (int j = lane; j < NTOK; j += 32) m = fmaxf(m, row[j]);
        #pragma unroll
        for (int o = 16; o; o >>= 1) m = fmaxf(m, __shfl_xor_sync(~0u, m, o));
        float s = 0.f;
        for (int j = lane; j < NTOK; j += 32) {
            float e = __expf(row[j] - m); row[j] = e; s += e;
        }
        #pragma unroll
        for (int o = 16; o; o >>= 1) s += __shfl_xor_sync(~0u, s, o);
        float inv = 1.f / s;
        for (int j = lane; j < NTOK; j += 32) row[j] *= inv;
    }
    __syncthreads();

    // ---- O = P @ V via 3xTF32 mma (warps 0..6; 4 n8 tiles; 13 k8 steps)
    if (warp < 7) {
        int mt = warp * 16;
        float acc[4][4] = {};
        #pragma unroll
        for (int ks = 0; ks < 13; ks++) {
            int kk = ks * 8;
            float a0 = sS[(mt + g) * SST + kk + tg];
            float a1 = sS[(mt + g + 8) * SST + kk + tg];
            float a2 = sS[(mt + g) * SST + kk + tg + 4];
            float a3 = sS[(mt + g + 8) * SST + kk + tg + 4];
            uint32_t ah[4] = {f2tf(a0), f2tf(a1), f2tf(a2), f2tf(a3)};
            uint32_t al[4] = {f2tf(a0 - __uint_as_float(ah[0])),
                              f2tf(a1 - __uint_as_float(ah[1])),
                              f2tf(a2 - __uint_as_float(ah[2])),
                              f2tf(a3 - __uint_as_float(ah[3]))};
            #pragma unroll
            for (int ni = 0; ni < 4; ni++) {
                float b0 = sv[(kk + tg) * QST + ni * 8 + g];
                float b1 = sv[(kk + tg + 4) * QST + ni * 8 + g];
                uint32_t bh[2] = {f2tf(b0), f2tf(b1)};
                uint32_t bl[2] = {f2tf(b0 - __uint_as_float(bh[0])),
                                  f2tf(b1 - __uint_as_float(bh[1]))};
                mma_tf32(acc[ni], ah, bh, acc[ni]);
                mma_tf32(acc[ni], ah, bl, acc[ni]);
                mma_tf32(acc[ni], al, bh, acc[ni]);
            }
        }
        float* outw = g_att + (size_t)w * NTOK * DIM + h * HD;
        #pragma unroll
        for (int ni = 0; ni < 4; ni++) {
            int c = ni * 8 + 2 * tg;
            int r0 = mt + g, r1 = mt + g + 8;
            if (r0 < NTOK)
                *(float2*)&outw[(size_t)r0 * DIM + c] = make_float2(acc[ni][0], acc[ni][1]);
            if (r1 < NTOK)
                *(float2*)&outw[(size_t)r1 * DIM + c] = make_float2(acc[ni][2], acc[ni][3]);
        }
    }
}

// ---------------- launch ----------------
extern "C" void kernel_launch(void* const* d_in, const int* in_sizes, int n_in,
                              void* d_out, int out_size) {
    const float* x      = (const float*)d_in[0];
    const float* qkv_w  = (const float*)d_in[1];
    const float* q_bias = (const float*)d_in[2];
    const float* v_bias = (const float*)d_in[3];
    const float* ls     = (const float*)d_in[4];
    const float* cpb_w1 = (const float*)d_in[5];
    const float* cpb_b1 = (const float*)d_in[6];
    const float* cpb_w2 = (const float*)d_in[7];
    const float* proj_w = (const float*)d_in[8];
    const float* proj_b = (const float*)d_in[9];
    float* out = (float*)d_out;

    float *qkv, *att, *bias768;
    cudaGetSymbolAddress((void**)&qkv,     g_qkv);
    cudaGetSymbolAddress((void**)&att,     g_att);
    cudaGetSymbolAddress((void**)&bias768, g_bias768);

    setup_small<<<1, 768>>>(q_bias, v_bias, ls);
    cpb_kernel<<<TBL, 512>>>(cpb_w1, cpb_b1, cpb_w2);

    cudaFuncSetAttribute(gemm_tc, cudaFuncAttributeMaxDynamicSharedMemorySize, GEMM_SMEM);

    // QKV: [200704,256] @ qkv_w[768,256]^T + bias768  (W consumed as native [N,K])
    gemm_tc<<<dim3(768 / 128, M_TOT / 128), 256, GEMM_SMEM>>>(x, qkv_w, bias768, qkv, 768);

    int smem_bytes = ATTN_SMEM_FLOATS * (int)sizeof(float);
    cudaFuncSetAttribute(attn_kernel, cudaFuncAttributeMaxDynamicSharedMemorySize, smem_bytes);
    attn_kernel<<<BW * NH, 256, smem_bytes>>>();

    // proj: [200704,256] @ proj_w[256,256]^T + proj_b
    gemm_tc<<<dim3(256 / 128, M_TOT / 128), 256, GEMM_SMEM>>>(att, proj_w, proj_b, out, 256);
}

// round 12
// speedup vs baseline: 1.3485x; 1.3485x over previous
#include <cuda_runtime.h>
#include <math.h>
#include <stdint.h>

#define DIM   256
#define NH    8
#define HD    32
#define NTOK  98
#define BW    2048
#define TBL   507                 // (2*2-1)*(2*7-1)*(2*7-1)
#define M_TOT (BW*NTOK)           // 200704
#define QST   36                  // q/k/v smem row stride
#define MPAD  112                 // tokens padded to 7 x m16

// ---------------- device scratch (no allocations allowed) ----------------
__device__ float g_qkv[(size_t)BW * NTOK * 3 * DIM];   // 616 MB
__device__ float g_att[(size_t)BW * NTOK * DIM];       // 205 MB
__device__ float g_bt[TBL * NH];                       // 16*sigmoid(cpb) table
__device__ float g_bias768[3 * DIM];
__device__ float g_scale[NH];

// ---------------- setup: fused bias + per-head logit scale ----------------
__global__ void setup_small(const float* __restrict__ qb,
                            const float* __restrict__ vb,
                            const float* __restrict__ ls) {
    int t = threadIdx.x;                       // 768 threads
    float b;
    if (t < 256)       b = qb[t];
    else if (t < 512)  b = 0.f;
    else               b = vb[t - 512];
    g_bias768[t] = b;
    if (t < NH) g_scale[t] = expf(fminf(ls[t], 4.6051701860f)); // log(100)
}

// ---------------- CPB MLP: table -> relu -> w2 -> 16*sigmoid ----------------
__global__ void cpb_kernel(const float* __restrict__ w1, const float* __restrict__ b1,
                           const float* __restrict__ w2) {
    __shared__ float hid[512];
    int t = blockIdx.x;                        // 0..506
    int a = t / 169, rem = t % 169, b = rem / 13, c = rem % 13;
    const float eps = 1e-6f;
    float ga = (float)(a - 1) / (2.f - (1.f - eps)) * 8.f;
    float gb = (float)(b - 6) / (7.f - (1.f - eps)) * 8.f;
    float gc = (float)(c - 6) / (7.f - (1.f - eps)) * 8.f;
    const float il8 = 1.f / log2f(8.f);
    ga = copysignf(log2f(fabsf(ga) + 1.f) * il8, ga);
    gb = copysignf(log2f(fabsf(gb) + 1.f) * il8, gb);
    gc = copysignf(log2f(fabsf(gc) + 1.f) * il8, gc);
    int j = threadIdx.x;                       // 512 threads
    float hv = ga * w1[j * 3 + 0] + gb * w1[j * 3 + 1] + gc * w1[j * 3 + 2] + b1[j];
    hid[j] = fmaxf(hv, 0.f);
    __syncthreads();
    if (j < NH) {
        float acc = 0.f;
        for (int q = 0; q < 512; q++) acc += hid[q] * w2[j * 512 + q];
        g_bt[t * NH + j] = 16.f / (1.f + expf(-acc));
    }
}

// ---------------- tf32 helpers ----------------
__device__ __forceinline__ uint32_t f2tf(float x) {
    uint32_t u;
    asm("cvt.rna.tf32.f32 %0, %1;" : "=r"(u) : "f"(x));
    return u;
}

__device__ __forceinline__ uint32_t smem_u32(const void* p) {
    uint32_t a;
    asm("{ .reg .u64 t; cvta.to.shared.u64 t, %1; cvt.u32.u64 %0, t; }"
        : "=r"(a) : "l"(p));
    return a;
}

__device__ __forceinline__ void mma_tf32(float* d, const uint32_t* a,
                                         const uint32_t* b, const float* c) {
    asm volatile(
        "mma.sync.aligned.m16n8k8.row.col.f32.tf32.tf32.f32 "
        "{%0,%1,%2,%3}, {%4,%5,%6,%7}, {%8,%9}, {%10,%11,%12,%13};\n"
        : "=f"(d[0]), "=f"(d[1]), "=f"(d[2]), "=f"(d[3])
        : "r"(a[0]), "r"(a[1]), "r"(a[2]), "r"(a[3]),
          "r"(b[0]), "r"(b[1]),
          "f"(c[0]), "f"(c[1]), "f"(c[2]), "f"(c[3]));
}

#define CP16(dst, src) \
    asm volatile("cp.async.cg.shared.global [%0], [%1], 16;" :: "r"(dst), "l"(src))
#define CP_COMMIT() asm volatile("cp.async.commit_group;" ::: "memory")
#define CP_WAIT1()  asm volatile("cp.async.wait_group 1;" ::: "memory")
#define CP_WAIT0()  asm volatile("cp.async.wait_group 0;" ::: "memory")

// ---------------- tf32 mma.sync GEMM, cp.async 3-stage (unchanged) --------
#define KCH    32
#define NCHUNK 8
#define RST    36
#define STG    (128 * RST)
#define GEMM_SMEM (3 * 2 * STG * 4)         // 110592 bytes

__global__ __launch_bounds__(256) void gemm_tc(const float* __restrict__ A,
                                               const float* __restrict__ W,
                                               const float* __restrict__ bias,
                                               float* __restrict__ C, int Nout) {
    extern __shared__ float sm[];
    uint32_t sbase = smem_u32(sm);
    int tid = threadIdx.x;
    int wid = tid >> 5, lane = tid & 31;
    int g = lane >> 2, tg = lane & 3;
    int m0 = blockIdx.y * 128, n0 = blockIdx.x * 128;
    int wm = (wid & 3) * 32, wn = (wid >> 2) * 64;

    float acc[2][8][4] = {};

    int row0 = tid >> 3, seg = tid & 7;
    const float* Ap = A + (size_t)(m0 + row0) * 256 + seg * 4;
    const float* Wp = W + (size_t)(n0 + row0) * 256 + seg * 4;

    #define STAGE_CHUNK(cc) do {                                                  \
        int _st = (cc) % 3;                                                       \
        uint32_t _ab = sbase + (uint32_t)(_st * 2 * STG) * 4;                     \
        uint32_t _bb = _ab + (uint32_t)STG * 4;                                   \
        _Pragma("unroll")                                                         \
        for (int _j = 0; _j < 4; _j++) {                                          \
            int _r = row0 + _j * 32;                                              \
            uint32_t _o = (uint32_t)(_r * RST + seg * 4) * 4;                     \
            CP16(_ab + _o, Ap + (size_t)_j * 32 * 256 + (cc) * KCH);              \
            CP16(_bb + _o, Wp + (size_t)_j * 32 * 256 + (cc) * KCH);              \
        }                                                                         \
        CP_COMMIT();                                                              \
    } while (0)

    STAGE_CHUNK(0);
    STAGE_CHUNK(1);

    for (int c = 0; c < NCHUNK; c++) {
        if (c == NCHUNK - 1) CP_WAIT0(); else CP_WAIT1();
        __syncthreads();
        if (c + 2 < NCHUNK) STAGE_CHUNK(c + 2);

        const float* As = sm + (c % 3) * 2 * STG;
        const float* Bs = As + STG;
        #pragma unroll
        for (int kk = 0; kk < KCH; kk += 8) {
            uint32_t af[2][4];
            #pragma unroll
            for (int mi = 0; mi < 2; mi++) {
                int r = wm + mi * 16 + g;
                af[mi][0] = f2tf(As[r * RST + kk + tg]);
                af[mi][1] = f2tf(As[(r + 8) * RST + kk + tg]);
                af[mi][2] = f2tf(As[r * RST + kk + tg + 4]);
                af[mi][3] = f2tf(As[(r + 8) * RST + kk + tg + 4]);
            }
            uint32_t bf[8][2];
            #pragma unroll
            for (int ni = 0; ni < 8; ni++) {
                int n = wn + ni * 8 + g;
                bf[ni][0] = f2tf(Bs[n * RST + kk + tg]);
                bf[ni][1] = f2tf(Bs[n * RST + kk + tg + 4]);
            }
            #pragma unroll
            for (int mi = 0; mi < 2; mi++)
                #pragma unroll
                for (int ni = 0; ni < 8; ni++)
                    mma_tf32(acc[mi][ni], af[mi], bf[ni], acc[mi][ni]);
        }
        __syncthreads();
    }

    #pragma unroll
    for (int mi = 0; mi < 2; mi++) {
        #pragma unroll
        for (int ni = 0; ni < 8; ni++) {
            int row = m0 + wm + mi * 16 + g;
            int col = n0 + wn + ni * 8 + 2 * tg;
            float b0v = bias[col], b1v = bias[col + 1];
            *(float2*)&C[(size_t)row * Nout + col] =
                make_float2(acc[mi][ni][0] + b0v, acc[mi][ni][1] + b1v);
            *(float2*)&C[(size_t)(row + 8) * Nout + col] =
                make_float2(acc[mi][ni][2] + b0v, acc[mi][ni][3] + b1v);
        }
    }
}

// ---------------- fused attention: register-resident S + quad softmax ------
// smem floats: 3*112*36 + 507 + 2*112 = 12827  (51308 bytes)
#define ATTN_SMEM_FLOATS (3 * MPAD * QST + TBL + 2 * MPAD)

__global__ __launch_bounds__(224, 2) void attn_kernel() {
    extern __shared__ float sm[];
    float* sq  = sm;
    float* sk  = sq + MPAD * QST;
    float* sv  = sk + MPAD * QST;
    float* sbt = sv + MPAD * QST;          // 507
    float* siq = sbt + TBL;                // 112 row scales (q, incl. logit scale)
    float* sik = siq + MPAD;               // 112 col scales (k)
    int bx = blockIdx.x;
    int w = bx >> 3, h = bx & 7;
    int tid = threadIdx.x;
    int warp = tid >> 5, lane = tid & 31;
    int g = lane >> 2, tg = lane & 3;

    // fill q/k/v (rows 98..111 zero); float4 both sides
    const float* base = g_qkv + (size_t)w * NTOK * 768 + h * HD;
    for (int e = tid; e < MPAD * 8; e += 224) {
        int n = e >> 3, d4 = (e & 7) * 4;
        float4 vq, vk, vv;
        if (n < NTOK) {
            const float* r = base + (size_t)n * 768;
            vq = *(const float4*)(r + d4);
            vk = *(const float4*)(r + 256 + d4);
            vv = *(const float4*)(r + 512 + d4);
        } else {
            vq = make_float4(0.f, 0.f, 0.f, 0.f); vk = vq; vv = vq;
        }
        *(float4*)&sq[n * QST + d4] = vq;
        *(float4*)&sk[n * QST + d4] = vk;
        *(float4*)&sv[n * QST + d4] = vv;
    }
    for (int e = tid; e < TBL; e += 224) sbt[e] = g_bt[e * NH + h];
    __syncthreads();

    // row norms -> scale factors (raw q/k stay in smem; scales applied post-mma)
    float scale = g_scale[h];
    {
        int r = (tid < MPAD) ? tid : tid - MPAD;     // 224 threads = 112 q + 112 k
        const float* src = (tid < MPAD) ? &sq[r * QST] : &sk[r * QST];
        float nn = 0.f;
        #pragma unroll
        for (int d4 = 0; d4 < HD; d4 += 4) {
            float4 v = *(const float4*)(src + d4);
            nn += v.x * v.x + v.y * v.y + v.z * v.z + v.w * v.w;
        }
        float inv = 1.f / fmaxf(sqrtf(nn), 1e-12f);
        if (tid < MPAD) siq[r] = scale * inv; else sik[r] = inv;
    }
    __syncthreads();

    // ---- S = q @ k^T via 3xTF32 mma; accumulators stay in registers
    int mt = warp * 16;                      // 7 warps x m16 = 112 rows
    float acc[13][4];
    #pragma unroll
    for (int ni = 0; ni < 13; ni++)
        #pragma unroll
        for (int e = 0; e < 4; e++) acc[ni][e] = 0.f;

    #pragma unroll
    for (int ks = 0; ks < 4; ks++) {
        int kk = ks * 8;
        float a0 = sq[(mt + g) * QST + kk + tg];
        float a1 = sq[(mt + g + 8) * QST + kk + tg];
        float a2 = sq[(mt + g) * QST + kk + tg + 4];
        float a3 = sq[(mt + g + 8) * QST + kk + tg + 4];
        uint32_t ah[4] = {f2tf(a0), f2tf(a1), f2tf(a2), f2tf(a3)};
        uint32_t al[4] = {f2tf(a0 - __uint_as_float(ah[0])),
                          f2tf(a1 - __uint_as_float(ah[1])),
                          f2tf(a2 - __uint_as_float(ah[2])),
                          f2tf(a3 - __uint_as_float(ah[3]))};
        #pragma unroll
        for (int ni = 0; ni < 13; ni++) {
            float b0 = sk[(ni * 8 + g) * QST + kk + tg];
            float b1 = sk[(ni * 8 + g) * QST + kk + tg + 4];
            uint32_t bh[2] = {f2tf(b0), f2tf(b1)};
            uint32_t bl[2] = {f2tf(b0 - __uint_as_float(bh[0])),
                              f2tf(b1 - __uint_as_float(bh[1]))};
            mma_tf32(acc[ni], ah, bh, acc[ni]);
            mma_tf32(acc[ni], ah, bl, acc[ni]);
            mma_tf32(acc[ni], al, bh, acc[ni]);
        }
    }

    // ---- in-register epilogue: scale + relative-position bias + pad mask
    int r0 = mt + g, r1 = r0 + 8;
    float sq0 = siq[r0], sq1 = siq[r1];
    int di0 = 0, hi0 = 0, wi0 = 0, di1 = 0, hi1 = 0, wi1 = 0;
    if (r0 < NTOK) { di0 = r0 / 49; int rr = r0 % 49; hi0 = rr / 7; wi0 = rr % 7; }
    if (r1 < NTOK) { di1 = r1 / 49; int rr = r1 % 49; hi1 = rr / 7; wi1 = rr % 7; }
    #pragma unroll
    for (int ni = 0; ni < 13; ni++) {
        #pragma unroll
        for (int u = 0; u < 2; u++) {
            int c = ni * 8 + 2 * tg + u;
            if (c < NTOK) {
                int dj = c / 49, rj = c % 49, hj = rj / 7, wj = rj % 7;
                float skc = sik[c];
                int base0 = -dj * 169 - hj * 13 - wj + 169 + 6 * 13 + 6;
                if (r0 < NTOK)
                    acc[ni][u] = acc[ni][u] * sq0 * skc +
                                 sbt[di0 * 169 + hi0 * 13 + wi0 + base0];
                else acc[ni][u] = -1e30f;
                if (r1 < NTOK)
                    acc[ni][u + 2] = acc[ni][u + 2] * sq1 * skc +
                                     sbt[di1 * 169 + hi1 * 13 + wi1 + base0];
                else acc[ni][u + 2] = -1e30f;
            } else {
                acc[ni][u] = -1e30f;
                acc[ni][u + 2] = -1e30f;
            }
        }
    }

    // ---- softmax in registers (rows r0, r1 live in quad: shfl_xor 1,2)
    float m0 = -1e30f, m1 = -1e30f;
    #pragma unroll
    for (int ni = 0; ni < 13; ni++) {
        m0 = fmaxf(m0, fmaxf(acc[ni][0], acc[ni][1]));
        m1 = fmaxf(m1, fmaxf(acc[ni][2], acc[ni][3]));
    }
    m0 = fmaxf(m0, __shfl_xor_sync(~0u, m0, 1)); m0 = fmaxf(m0, __shfl_xor_sync(~0u, m0, 2));
    m1 = fmaxf(m1, __shfl_xor_sync(~0u, m1, 1)); m1 = fmaxf(m1, __shfl_xor_sync(~0u, m1, 2));
    float s0 = 0.f, s1 = 0.f;
    #pragma unroll
    for (int ni = 0; ni < 13; ni++) {
        acc[ni][0] = __expf(acc[ni][0] - m0); s0 += acc[ni][0];
        acc[ni][1] = __expf(acc[ni][1] - m0); s0 += acc[ni][1];
        acc[ni][2] = __expf(acc[ni][2] - m1); s1 += acc[ni][2];
        acc[ni][3] = __expf(acc[ni][3] - m1); s1 += acc[ni][3];
    }
    s0 += __shfl_xor_sync(~0u, s0, 1); s0 += __shfl_xor_sync(~0u, s0, 2);
    s1 += __shfl_xor_sync(~0u, s1, 1); s1 += __shfl_xor_sync(~0u, s1, 2);
    float i0 = 1.f / s0, i1 = 1.f / s1;
    #pragma unroll
    for (int ni = 0; ni < 13; ni++) {
        acc[ni][0] *= i0; acc[ni][1] *= i0;
        acc[ni][2] *= i1; acc[ni][3] *= i1;
    }

    // ---- O = P @ V via 3xTF32; P fragments built with quad shuffles
    float oacc[4][4];
    #pragma unroll
    for (int ni = 0; ni < 4; ni++)
        #pragma unroll
        for (int e = 0; e < 4; e++) oacc[ni][e] = 0.f;

    int qbase = lane & ~3;
    int L1 = qbase + (tg >> 1), L2 = L1 + 2;
    bool hi = (tg & 1);
    #pragma unroll
    for (int ks = 0; ks < 13; ks++) {
        int kk = ks * 8;
        float e0a = __shfl_sync(~0u, acc[ks][0], L1), e1a = __shfl_sync(~0u, acc[ks][1], L1);
        float e2a = __shfl_sync(~0u, acc[ks][2], L1), e3a = __shfl_sync(~0u, acc[ks][3], L1);
        float e0b = __shfl_sync(~0u, acc[ks][0], L2), e1b = __shfl_sync(~0u, acc[ks][1], L2);
        float e2b = __shfl_sync(~0u, acc[ks][2], L2), e3b = __shfl_sync(~0u, acc[ks][3], L2);
        float a0 = hi ? e1a : e0a;    // P[r0, kk+tg]
        float a1 = hi ? e3a : e2a;    // P[r1, kk+tg]
        float a2 = hi ? e1b : e0b;    // P[r0, kk+tg+4]
        float a3 = hi ? e3b : e2b;    // P[r1, kk+tg+4]
        uint32_t ah[4] = {f2tf(a0), f2tf(a1), f2tf(a2), f2tf(a3)};
        uint32_t al[4] = {f2tf(a0 - __uint_as_float(ah[0])),
                          f2tf(a1 - __uint_as_float(ah[1])),
                          f2tf(a2 - __uint_as_float(ah[2])),
                          f2tf(a3 - __uint_as_float(ah[3]))};
        #pragma unroll
        for (int ni = 0; ni < 4; ni++) {
            float b0 = sv[(kk + tg) * QST + ni * 8 + g];
            float b1 = sv[(kk + tg + 4) * QST + ni * 8 + g];
            uint32_t bh[2] = {f2tf(b0), f2tf(b1)};
            uint32_t bl[2] = {f2tf(b0 - __uint_as_float(bh[0])),
                              f2tf(b1 - __uint_as_float(bh[1]))};
            mma_tf32(oacc[ni], ah, bh, oacc[ni]);
            mma_tf32(oacc[ni], ah, bl, oacc[ni]);
            mma_tf32(oacc[ni], al, bh, oacc[ni]);
        }
    }
    float* outw = g_att + (size_t)w * NTOK * DIM + h * HD;
    #pragma unroll
    for (int ni = 0; ni < 4; ni++) {
        int c = ni * 8 + 2 * tg;
        if (r0 < NTOK)
            *(float2*)&outw[(size_t)r0 * DIM + c] = make_float2(oacc[ni][0], oacc[ni][1]);
        if (r1 < NTOK)
            *(float2*)&outw[(size_t)r1 * DIM + c] = make_float2(oacc[ni][2], oacc[ni][3]);
    }
}

// ---------------- launch ----------------
extern "C" void kernel_launch(void* const* d_in, const int* in_sizes, int n_in,
                              void* d_out, int out_size) {
    const float* x      = (const float*)d_in[0];
    const float* qkv_w  = (const float*)d_in[1];
    const float* q_bias = (const float*)d_in[2];
    const float* v_bias = (const float*)d_in[3];
    const float* ls     = (const float*)d_in[4];
    const float* cpb_w1 = (const float*)d_in[5];
    const float* cpb_b1 = (const float*)d_in[6];
    const float* cpb_w2 = (const float*)d_in[7];
    const float* proj_w = (const float*)d_in[8];
    const float* proj_b = (const float*)d_in[9];
    float* out = (float*)d_out;

    float *qkv, *att, *bias768;
    cudaGetSymbolAddress((void**)&qkv,     g_qkv);
    cudaGetSymbolAddress((void**)&att,     g_att);
    cudaGetSymbolAddress((void**)&bias768, g_bias768);

    setup_small<<<1, 768>>>(q_bias, v_bias, ls);
    cpb_kernel<<<TBL, 512>>>(cpb_w1, cpb_b1, cpb_w2);

    cudaFuncSetAttribute(gemm_tc, cudaFuncAttributeMaxDynamicSharedMemorySize, GEMM_SMEM);

    // QKV: [200704,256] @ qkv_w[768,256]^T + bias768
    gemm_tc<<<dim3(768 / 128, M_TOT / 128), 256, GEMM_SMEM>>>(x, qkv_w, bias768, qkv, 768);

    int smem_bytes = ATTN_SMEM_FLOATS * (int)sizeof(float);
    cudaFuncSetAttribute(attn_kernel, cudaFuncAttributeMaxDynamicSharedMemorySize, smem_bytes);
    attn_kernel<<<BW * NH, 224, smem_bytes>>>();

    // proj: [200704,256] @ proj_w[256,256]^T + proj_b
    gemm_tc<<<dim3(256 / 128, M_TOT / 128), 256, GEMM_SMEM>>>(att, proj_w, proj_b, out, 256);
}

// round 13
// speedup vs baseline: 1.4280x; 1.0589x over previous
#include <cuda_runtime.h>
#include <math.h>
#include <stdint.h>

#define DIM   256
#define NH    8
#define HD    32
#define NTOK  98
#define BW    2048
#define TBL   507                 // (2*2-1)*(2*7-1)*(2*7-1)
#define M_TOT (BW*NTOK)           // 200704
#define QST   36                  // q/k/v smem row stride
#define MPAD  112                 // tokens padded to 7 x m16

// ---------------- device scratch (no allocations allowed) ----------------
__device__ float g_qkv[(size_t)BW * NTOK * 3 * DIM];   // 616 MB
__device__ float g_att[(size_t)BW * NTOK * DIM];       // 205 MB
__device__ float g_bt[TBL * NH];                       // 16*sigmoid(cpb) table
__device__ float g_bias768[3 * DIM];
__device__ float g_scale[NH];

// ---------------- setup: fused bias + per-head logit scale ----------------
__global__ void setup_small(const float* __restrict__ qb,
                            const float* __restrict__ vb,
                            const float* __restrict__ ls) {
    int t = threadIdx.x;                       // 768 threads
    float b;
    if (t < 256)       b = qb[t];
    else if (t < 512)  b = 0.f;
    else               b = vb[t - 512];
    g_bias768[t] = b;
    if (t < NH) g_scale[t] = expf(fminf(ls[t], 4.6051701860f)); // log(100)
}

// ---------------- CPB MLP: table -> relu -> w2 -> 16*sigmoid ----------------
__global__ void cpb_kernel(const float* __restrict__ w1, const float* __restrict__ b1,
                           const float* __restrict__ w2) {
    __shared__ float hid[512];
    int t = blockIdx.x;                        // 0..506
    int a = t / 169, rem = t % 169, b = rem / 13, c = rem % 13;
    const float eps = 1e-6f;
    float ga = (float)(a - 1) / (2.f - (1.f - eps)) * 8.f;
    float gb = (float)(b - 6) / (7.f - (1.f - eps)) * 8.f;
    float gc = (float)(c - 6) / (7.f - (1.f - eps)) * 8.f;
    const float il8 = 1.f / log2f(8.f);
    ga = copysignf(log2f(fabsf(ga) + 1.f) * il8, ga);
    gb = copysignf(log2f(fabsf(gb) + 1.f) * il8, gb);
    gc = copysignf(log2f(fabsf(gc) + 1.f) * il8, gc);
    int j = threadIdx.x;                       // 512 threads
    float hv = ga * w1[j * 3 + 0] + gb * w1[j * 3 + 1] + gc * w1[j * 3 + 2] + b1[j];
    hid[j] = fmaxf(hv, 0.f);
    __syncthreads();
    if (j < NH) {
        float acc = 0.f;
        for (int q = 0; q < 512; q++) acc += hid[q] * w2[j * 512 + q];
        g_bt[t * NH + j] = 16.f / (1.f + expf(-acc));
    }
}

// ---------------- tf32 helpers ----------------
__device__ __forceinline__ uint32_t f2tf(float x) {
    uint32_t u;
    asm("cvt.rna.tf32.f32 %0, %1;" : "=r"(u) : "f"(x));
    return u;
}

__device__ __forceinline__ uint32_t smem_u32(const void* p) {
    uint32_t a;
    asm("{ .reg .u64 t; cvta.to.shared.u64 t, %1; cvt.u32.u64 %0, t; }"
        : "=r"(a) : "l"(p));
    return a;
}

__device__ __forceinline__ void mma_tf32(float* d, const uint32_t* a,
                                         const uint32_t* b, const float* c) {
    asm volatile(
        "mma.sync.aligned.m16n8k8.row.col.f32.tf32.tf32.f32 "
        "{%0,%1,%2,%3}, {%4,%5,%6,%7}, {%8,%9}, {%10,%11,%12,%13};\n"
        : "=f"(d[0]), "=f"(d[1]), "=f"(d[2]), "=f"(d[3])
        : "r"(a[0]), "r"(a[1]), "r"(a[2]), "r"(a[3]),
          "r"(b[0]), "r"(b[1]),
          "f"(c[0]), "f"(c[1]), "f"(c[2]), "f"(c[3]));
}

#define CP16(dst, src) \
    asm volatile("cp.async.cg.shared.global [%0], [%1], 16;" :: "r"(dst), "l"(src))
#define CP_COMMIT() asm volatile("cp.async.commit_group;" ::: "memory")
#define CP_WAIT1()  asm volatile("cp.async.wait_group 1;" ::: "memory")
#define CP_WAIT0()  asm volatile("cp.async.wait_group 0;" ::: "memory")

// ---------------- tf32 mma.sync GEMM, cp.async 3-stage (unchanged) --------
#define KCH    32
#define NCHUNK 8
#define RST    36
#define STG    (128 * RST)
#define GEMM_SMEM (3 * 2 * STG * 4)         // 110592 bytes

__global__ __launch_bounds__(256) void gemm_tc(const float* __restrict__ A,
                                               const float* __restrict__ W,
                                               const float* __restrict__ bias,
                                               float* __restrict__ C, int Nout) {
    extern __shared__ float sm[];
    uint32_t sbase = smem_u32(sm);
    int tid = threadIdx.x;
    int wid = tid >> 5, lane = tid & 31;
    int g = lane >> 2, tg = lane & 3;
    int m0 = blockIdx.y * 128, n0 = blockIdx.x * 128;
    int wm = (wid & 3) * 32, wn = (wid >> 2) * 64;

    float acc[2][8][4] = {};

    int row0 = tid >> 3, seg = tid & 7;
    const float* Ap = A + (size_t)(m0 + row0) * 256 + seg * 4;
    const float* Wp = W + (size_t)(n0 + row0) * 256 + seg * 4;

    #define STAGE_CHUNK(cc) do {                                                  \
        int _st = (cc) % 3;                                                       \
        uint32_t _ab = sbase + (uint32_t)(_st * 2 * STG) * 4;                     \
        uint32_t _bb = _ab + (uint32_t)STG * 4;                                   \
        _Pragma("unroll")                                                         \
        for (int _j = 0; _j < 4; _j++) {                                          \
            int _r = row0 + _j * 32;                                              \
            uint32_t _o = (uint32_t)(_r * RST + seg * 4) * 4;                     \
            CP16(_ab + _o, Ap + (size_t)_j * 32 * 256 + (cc) * KCH);              \
            CP16(_bb + _o, Wp + (size_t)_j * 32 * 256 + (cc) * KCH);              \
        }                                                                         \
        CP_COMMIT();                                                              \
    } while (0)

    STAGE_CHUNK(0);
    STAGE_CHUNK(1);

    for (int c = 0; c < NCHUNK; c++) {
        if (c == NCHUNK - 1) CP_WAIT0(); else CP_WAIT1();
        __syncthreads();
        if (c + 2 < NCHUNK) STAGE_CHUNK(c + 2);

        const float* As = sm + (c % 3) * 2 * STG;
        const float* Bs = As + STG;
        #pragma unroll
        for (int kk = 0; kk < KCH; kk += 8) {
            uint32_t af[2][4];
            #pragma unroll
            for (int mi = 0; mi < 2; mi++) {
                int r = wm + mi * 16 + g;
                af[mi][0] = f2tf(As[r * RST + kk + tg]);
                af[mi][1] = f2tf(As[(r + 8) * RST + kk + tg]);
                af[mi][2] = f2tf(As[r * RST + kk + tg + 4]);
                af[mi][3] = f2tf(As[(r + 8) * RST + kk + tg + 4]);
            }
            uint32_t bf[8][2];
            #pragma unroll
            for (int ni = 0; ni < 8; ni++) {
                int n = wn + ni * 8 + g;
                bf[ni][0] = f2tf(Bs[n * RST + kk + tg]);
                bf[ni][1] = f2tf(Bs[n * RST + kk + tg + 4]);
            }
            #pragma unroll
            for (int mi = 0; mi < 2; mi++)
                #pragma unroll
                for (int ni = 0; ni < 8; ni++)
                    mma_tf32(acc[mi][ni], af[mi], bf[ni], acc[mi][ni]);
        }
        __syncthreads();
    }

    #pragma unroll
    for (int mi = 0; mi < 2; mi++) {
        #pragma unroll
        for (int ni = 0; ni < 8; ni++) {
            int row = m0 + wm + mi * 16 + g;
            int col = n0 + wn + ni * 8 + 2 * tg;
            float b0v = bias[col], b1v = bias[col + 1];
            *(float2*)&C[(size_t)row * Nout + col] =
                make_float2(acc[mi][ni][0] + b0v, acc[mi][ni][1] + b1v);
            *(float2*)&C[(size_t)(row + 8) * Nout + col] =
                make_float2(acc[mi][ni][2] + b0v, acc[mi][ni][3] + b1v);
        }
    }
}

// ---------------- fused attention: pre-decomposed hi/lo + register softmax --
// smem floats: 6*112*36 + 507 + 2*112 = 24923  (99692 bytes)
#define ATTN_SMEM_FLOATS (6 * MPAD * QST + TBL + 2 * MPAD)

__global__ __launch_bounds__(224, 2) void attn_kernel() {
    extern __shared__ float sm[];
    float* qhi = sm;                       // raw q during fill, then tf32-hi bits
    float* qlo = qhi + MPAD * QST;
    float* khi = qlo + MPAD * QST;
    float* klo = khi + MPAD * QST;
    float* vhi = klo + MPAD * QST;
    float* vlo = vhi + MPAD * QST;
    float* sbt = vlo + MPAD * QST;         // 507
    float* siq = sbt + TBL;                // 112 row scales (q, incl. logit scale)
    float* sik = siq + MPAD;               // 112 col scales (k)
    const uint32_t* qhiU = (const uint32_t*)qhi;
    const uint32_t* qloU = (const uint32_t*)qlo;
    const uint32_t* khiU = (const uint32_t*)khi;
    const uint32_t* kloU = (const uint32_t*)klo;
    const uint32_t* vhiU = (const uint32_t*)vhi;
    const uint32_t* vloU = (const uint32_t*)vlo;

    int bx = blockIdx.x;
    int w = bx >> 3, h = bx & 7;
    int tid = threadIdx.x;
    int warp = tid >> 5, lane = tid & 31;
    int g = lane >> 2, tg = lane & 3;

    // fill raw q/k/v into the *hi arrays (rows 98..111 zero)
    const float* base = g_qkv + (size_t)w * NTOK * 768 + h * HD;
    for (int e = tid; e < MPAD * 8; e += 224) {
        int n = e >> 3, d4 = (e & 7) * 4;
        float4 vq, vk, vv;
        if (n < NTOK) {
            const float* r = base + (size_t)n * 768;
            vq = *(const float4*)(r + d4);
            vk = *(const float4*)(r + 256 + d4);
            vv = *(const float4*)(r + 512 + d4);
        } else {
            vq = make_float4(0.f, 0.f, 0.f, 0.f); vk = vq; vv = vq;
        }
        *(float4*)&qhi[n * QST + d4] = vq;
        *(float4*)&khi[n * QST + d4] = vk;
        *(float4*)&vhi[n * QST + d4] = vv;
    }
    for (int e = tid; e < TBL; e += 224) sbt[e] = g_bt[e * NH + h];
    __syncthreads();

    // row norms -> scale factors
    float scale = g_scale[h];
    {
        int r = (tid < MPAD) ? tid : tid - MPAD;     // 224 threads = 112 q + 112 k
        const float* src = (tid < MPAD) ? &qhi[r * QST] : &khi[r * QST];
        float nn = 0.f;
        #pragma unroll
        for (int d4 = 0; d4 < HD; d4 += 4) {
            float4 v = *(const float4*)(src + d4);
            nn += v.x * v.x + v.y * v.y + v.z * v.z + v.w * v.w;
        }
        float inv = 1.f / fmaxf(sqrtf(nn), 1e-12f);
        if (tid < MPAD) siq[r] = scale * inv; else sik[r] = inv;
    }
    __syncthreads();

    // one-time hi/lo decomposition (scales folded into q, k pre-conversion)
    #define DECOMP4(HI, LO, off, sc) do {                                        \
        float4 _r = *(const float4*)&HI[off];                                    \
        uint4 _h, _l;                                                            \
        _h.x = f2tf(_r.x * sc); _l.x = f2tf(_r.x * sc - __uint_as_float(_h.x));  \
        _h.y = f2tf(_r.y * sc); _l.y = f2tf(_r.y * sc - __uint_as_float(_h.y));  \
        _h.z = f2tf(_r.z * sc); _l.z = f2tf(_r.z * sc - __uint_as_float(_h.z));  \
        _h.w = f2tf(_r.w * sc); _l.w = f2tf(_r.w * sc - __uint_as_float(_h.w));  \
        *(uint4*)&HI[off] = _h; *(uint4*)&LO[off] = _l;                          \
    } while (0)

    for (int e = tid; e < MPAD * 8; e += 224) {
        int n = e >> 3, d4 = (e & 7) * 4;
        int off = n * QST + d4;
        float fq = siq[n], fk = sik[n];
        DECOMP4(qhi, qlo, off, fq);
        DECOMP4(khi, klo, off, fk);
        DECOMP4(vhi, vlo, off, 1.f);
    }
    __syncthreads();

    // ---- S = qn @ kn^T via 3xTF32 mma; pure LDS + mma inner loop
    int mt = warp * 16;                      // 7 warps x m16 = 112 rows
    float acc[13][4];
    #pragma unroll
    for (int ni = 0; ni < 13; ni++)
        #pragma unroll
        for (int e = 0; e < 4; e++) acc[ni][e] = 0.f;

    #pragma unroll
    for (int ks = 0; ks < 4; ks++) {
        int kk = ks * 8;
        int o0 = (mt + g) * QST + kk + tg, o1 = (mt + g + 8) * QST + kk + tg;
        uint32_t ah[4] = {qhiU[o0], qhiU[o1], qhiU[o0 + 4], qhiU[o1 + 4]};
        uint32_t al[4] = {qloU[o0], qloU[o1], qloU[o0 + 4], qloU[o1 + 4]};
        #pragma unroll
        for (int ni = 0; ni < 13; ni++) {
            int ob = (ni * 8 + g) * QST + kk + tg;
            uint32_t bh[2] = {khiU[ob], khiU[ob + 4]};
            uint32_t bl[2] = {kloU[ob], kloU[ob + 4]};
            mma_tf32(acc[ni], ah, bh, acc[ni]);
            mma_tf32(acc[ni], ah, bl, acc[ni]);
            mma_tf32(acc[ni], al, bh, acc[ni]);
        }
    }

    // ---- in-register epilogue: + relative-position bias, pad mask
    int r0 = mt + g, r1 = r0 + 8;
    int di0 = 0, hi0 = 0, wi0 = 0, di1 = 0, hi1 = 0, wi1 = 0;
    if (r0 < NTOK) { di0 = r0 / 49; int rr = r0 % 49; hi0 = rr / 7; wi0 = rr % 7; }
    if (r1 < NTOK) { di1 = r1 / 49; int rr = r1 % 49; hi1 = rr / 7; wi1 = rr % 7; }
    #pragma unroll
    for (int ni = 0; ni < 13; ni++) {
        #pragma unroll
        for (int u = 0; u < 2; u++) {
            int c = ni * 8 + 2 * tg + u;
            if (c < NTOK) {
                int dj = c / 49, rj = c % 49, hj = rj / 7, wj = rj % 7;
                int base0 = -dj * 169 - hj * 13 - wj + 169 + 6 * 13 + 6;
                if (r0 < NTOK)
                    acc[ni][u] += sbt[di0 * 169 + hi0 * 13 + wi0 + base0];
                else acc[ni][u] = -1e30f;
                if (r1 < NTOK)
                    acc[ni][u + 2] += sbt[di1 * 169 + hi1 * 13 + wi1 + base0];
                else acc[ni][u + 2] = -1e30f;
            } else {
                acc[ni][u] = -1e30f;
                acc[ni][u + 2] = -1e30f;
            }
        }
    }

    // ---- softmax in registers (rows r0, r1 live in quad: shfl_xor 1,2)
    float m0 = -1e30f, m1 = -1e30f;
    #pragma unroll
    for (int ni = 0; ni < 13; ni++) {
        m0 = fmaxf(m0, fmaxf(acc[ni][0], acc[ni][1]));
        m1 = fmaxf(m1, fmaxf(acc[ni][2], acc[ni][3]));
    }
    m0 = fmaxf(m0, __shfl_xor_sync(~0u, m0, 1)); m0 = fmaxf(m0, __shfl_xor_sync(~0u, m0, 2));
    m1 = fmaxf(m1, __shfl_xor_sync(~0u, m1, 1)); m1 = fmaxf(m1, __shfl_xor_sync(~0u, m1, 2));
    float s0 = 0.f, s1 = 0.f;
    #pragma unroll
    for (int ni = 0; ni < 13; ni++) {
        acc[ni][0] = __expf(acc[ni][0] - m0); s0 += acc[ni][0];
        acc[ni][1] = __expf(acc[ni][1] - m0); s0 += acc[ni][1];
        acc[ni][2] = __expf(acc[ni][2] - m1); s1 += acc[ni][2];
        acc[ni][3] = __expf(acc[ni][3] - m1); s1 += acc[ni][3];
    }
    s0 += __shfl_xor_sync(~0u, s0, 1); s0 += __shfl_xor_sync(~0u, s0, 2);
    s1 += __shfl_xor_sync(~0u, s1, 1); s1 += __shfl_xor_sync(~0u, s1, 2);
    float i0 = 1.f / s0, i1 = 1.f / s1;
    #pragma unroll
    for (int ni = 0; ni < 13; ni++) {
        acc[ni][0] *= i0; acc[ni][1] *= i0;
        acc[ni][2] *= i1; acc[ni][3] *= i1;
    }

    // ---- O = P @ V via 3xTF32; P fragments built with quad shuffles
    float oacc[4][4];
    #pragma unroll
    for (int ni = 0; ni < 4; ni++)
        #pragma unroll
        for (int e = 0; e < 4; e++) oacc[ni][e] = 0.f;

    int qbase = lane & ~3;
    int L1 = qbase + (tg >> 1), L2 = L1 + 2;
    bool hi = (tg & 1);
    #pragma unroll
    for (int ks = 0; ks < 13; ks++) {
        int kk = ks * 8;
        float e0a = __shfl_sync(~0u, acc[ks][0], L1), e1a = __shfl_sync(~0u, acc[ks][1], L1);
        float e2a = __shfl_sync(~0u, acc[ks][2], L1), e3a = __shfl_sync(~0u, acc[ks][3], L1);
        float e0b = __shfl_sync(~0u, acc[ks][0], L2), e1b = __shfl_sync(~0u, acc[ks][1], L2);
        float e2b = __shfl_sync(~0u, acc[ks][2], L2), e3b = __shfl_sync(~0u, acc[ks][3], L2);
        float a0 = hi ? e1a : e0a;    // P[r0, kk+tg]
        float a1 = hi ? e3a : e2a;    // P[r1, kk+tg]
        float a2 = hi ? e1b : e0b;    // P[r0, kk+tg+4]
        float a3 = hi ? e3b : e2b;    // P[r1, kk+tg+4]
        uint32_t ah[4] = {f2tf(a0), f2tf(a1), f2tf(a2), f2tf(a3)};
        uint32_t al[4] = {f2tf(a0 - __uint_as_float(ah[0])),
                          f2tf(a1 - __uint_as_float(ah[1])),
                          f2tf(a2 - __uint_as_float(ah[2])),
                          f2tf(a3 - __uint_as_float(ah[3]))};
        #pragma unroll
        for (int ni = 0; ni < 4; ni++) {
            int ob0 = (kk + tg) * QST + ni * 8 + g;
            int ob1 = (kk + tg + 4) * QST + ni * 8 + g;
            uint32_t bh[2] = {vhiU[ob0], vhiU[ob1]};
            uint32_t bl[2] = {vloU[ob0], vloU[ob1]};
            mma_tf32(oacc[ni], ah, bh, oacc[ni]);
            mma_tf32(oacc[ni], ah, bl, oacc[ni]);
            mma_tf32(oacc[ni], al, bh, oacc[ni]);
        }
    }
    float* outw = g_att + (size_t)w * NTOK * DIM + h * HD;
    #pragma unroll
    for (int ni = 0; ni < 4; ni++) {
        int c = ni * 8 + 2 * tg;
        if (r0 < NTOK)
            *(float2*)&outw[(size_t)r0 * DIM + c] = make_float2(oacc[ni][0], oacc[ni][1]);
        if (r1 < NTOK)
            *(float2*)&outw[(size_t)r1 * DIM + c] = make_float2(oacc[ni][2], oacc[ni][3]);
    }
}

// ---------------- launch ----------------
extern "C" void kernel_launch(void* const* d_in, const int* in_sizes, int n_in,
                              void* d_out, int out_size) {
    const float* x      = (const float*)d_in[0];
    const float* qkv_w  = (const float*)d_in[1];
    const float* q_bias = (const float*)d_in[2];
    const float* v_bias = (const float*)d_in[3];
    const float* ls     = (const float*)d_in[4];
    const float* cpb_w1 = (const float*)d_in[5];
    const float* cpb_b1 = (const float*)d_in[6];
    const float* cpb_w2 = (const float*)d_in[7];
    const float* proj_w = (const float*)d_in[8];
    const float* proj_b = (const float*)d_in[9];
    float* out = (float*)d_out;

    float *qkv, *att, *bias768;
    cudaGetSymbolAddress((void**)&qkv,     g_qkv);
    cudaGetSymbolAddress((void**)&att,     g_att);
    cudaGetSymbolAddress((void**)&bias768, g_bias768);

    setup_small<<<1, 768>>>(q_bias, v_bias, ls);
    cpb_kernel<<<TBL, 512>>>(cpb_w1, cpb_b1, cpb_w2);

    cudaFuncSetAttribute(gemm_tc, cudaFuncAttributeMaxDynamicSharedMemorySize, GEMM_SMEM);

    // QKV: [200704,256] @ qkv_w[768,256]^T + bias768
    gemm_tc<<<dim3(768 / 128, M_TOT / 128), 256, GEMM_SMEM>>>(x, qkv_w, bias768, qkv, 768);

    int smem_bytes = ATTN_SMEM_FLOATS * (int)sizeof(float);
    cudaFuncSetAttribute(attn_kernel, cudaFuncAttributeMaxDynamicSharedMemorySize, smem_bytes);
    attn_kernel<<<BW * NH, 224, smem_bytes>>>();

    // proj: [200704,256] @ proj_w[256,256]^T + proj_b
    gemm_tc<<<dim3(256 / 128, M_TOT / 128), 256, GEMM_SMEM>>>(att, proj_w, proj_b, out, 256);
}

// round 15
// speedup vs baseline: 1.5086x; 1.0564x over previous
#include <cuda_runtime.h>
#include <math.h>
#include <stdint.h>

#define DIM   256
#define NH    8
#define HD    32
#define NTOK  98
#define BW    2048
#define TBL   507                 // (2*2-1)*(2*7-1)*(2*7-1)
#define M_TOT (BW*NTOK)           // 200704
#define QST   36                  // q/k/v smem row stride
#define MPAD  112                 // tokens padded to 7 x m16

// ---------------- device scratch (no allocations allowed) ----------------
__device__ float g_qkv[(size_t)BW * NTOK * 3 * DIM];   // 616 MB
__device__ float g_att[(size_t)BW * NTOK * DIM];       // 205 MB
__device__ float g_bt[TBL * NH];                       // 16*sigmoid(cpb) table
__device__ float g_bias768[3 * DIM];
__device__ float g_scale[NH];

// ---------------- setup: fused bias + per-head logit scale ----------------
__global__ void setup_small(const float* __restrict__ qb,
                            const float* __restrict__ vb,
                            const float* __restrict__ ls) {
    int t = threadIdx.x;                       // 768 threads
    float b;
    if (t < 256)       b = qb[t];
    else if (t < 512)  b = 0.f;
    else               b = vb[t - 512];
    g_bias768[t] = b;
    if (t < NH) g_scale[t] = expf(fminf(ls[t], 4.6051701860f)); // log(100)
}

// ---------------- CPB MLP: table -> relu -> w2 -> 16*sigmoid ----------------
__global__ void cpb_kernel(const float* __restrict__ w1, const float* __restrict__ b1,
                           const float* __restrict__ w2) {
    __shared__ float hid[512];
    int t = blockIdx.x;                        // 0..506
    int a = t / 169, rem = t % 169, b = rem / 13, c = rem % 13;
    const float eps = 1e-6f;
    float ga = (float)(a - 1) / (2.f - (1.f - eps)) * 8.f;
    float gb = (float)(b - 6) / (7.f - (1.f - eps)) * 8.f;
    float gc = (float)(c - 6) / (7.f - (1.f - eps)) * 8.f;
    const float il8 = 1.f / log2f(8.f);
    ga = copysignf(log2f(fabsf(ga) + 1.f) * il8, ga);
    gb = copysignf(log2f(fabsf(gb) + 1.f) * il8, gb);
    gc = copysignf(log2f(fabsf(gc) + 1.f) * il8, gc);
    int j = threadIdx.x;                       // 512 threads
    float hv = ga * w1[j * 3 + 0] + gb * w1[j * 3 + 1] + gc * w1[j * 3 + 2] + b1[j];
    hid[j] = fmaxf(hv, 0.f);
    __syncthreads();
    if (j < NH) {
        float acc = 0.f;
        for (int q = 0; q < 512; q++) acc += hid[q] * w2[j * 512 + q];
        g_bt[t * NH + j] = 16.f / (1.f + expf(-acc));
    }
}

// ---------------- tf32 helpers ----------------
__device__ __forceinline__ uint32_t f2tf(float x) {
    uint32_t u;
    asm("cvt.rna.tf32.f32 %0, %1;" : "=r"(u) : "f"(x));
    return u;
}

__device__ __forceinline__ uint32_t smem_u32(const void* p) {
    uint32_t a;
    asm("{ .reg .u64 t; cvta.to.shared.u64 t, %1; cvt.u32.u64 %0, t; }"
        : "=r"(a) : "l"(p));
    return a;
}

__device__ __forceinline__ void mma_tf32(float* d, const uint32_t* a,
                                         const uint32_t* b, const float* c) {
    asm volatile(
        "mma.sync.aligned.m16n8k8.row.col.f32.tf32.tf32.f32 "
        "{%0,%1,%2,%3}, {%4,%5,%6,%7}, {%8,%9}, {%10,%11,%12,%13};\n"
        : "=f"(d[0]), "=f"(d[1]), "=f"(d[2]), "=f"(d[3])
        : "r"(a[0]), "r"(a[1]), "r"(a[2]), "r"(a[3]),
          "r"(b[0]), "r"(b[1]),
          "f"(c[0]), "f"(c[1]), "f"(c[2]), "f"(c[3]));
}

#define CP16(dst, src) \
    asm volatile("cp.async.cg.shared.global [%0], [%1], 16;" :: "r"(dst), "l"(src))
#define CP_COMMIT() asm volatile("cp.async.commit_group;" ::: "memory")
#define CP_WAIT1()  asm volatile("cp.async.wait_group 1;" ::: "memory")
#define CP_WAIT0()  asm volatile("cp.async.wait_group 0;" ::: "memory")

// ---------------- tf32 mma.sync GEMM, cp.async 3-stage (unchanged) --------
#define KCH    32
#define NCHUNK 8
#define RST    36
#define STG    (128 * RST)
#define GEMM_SMEM (3 * 2 * STG * 4)         // 110592 bytes

__global__ __launch_bounds__(256) void gemm_tc(const float* __restrict__ A,
                                               const float* __restrict__ W,
                                               const float* __restrict__ bias,
                                               float* __restrict__ C, int Nout) {
    extern __shared__ float sm[];
    uint32_t sbase = smem_u32(sm);
    int tid = threadIdx.x;
    int wid = tid >> 5, lane = tid & 31;
    int g = lane >> 2, tg = lane & 3;
    int m0 = blockIdx.y * 128, n0 = blockIdx.x * 128;
    int wm = (wid & 3) * 32, wn = (wid >> 2) * 64;

    float acc[2][8][4] = {};

    int row0 = tid >> 3, seg = tid & 7;
    const float* Ap = A + (size_t)(m0 + row0) * 256 + seg * 4;
    const float* Wp = W + (size_t)(n0 + row0) * 256 + seg * 4;

    #define STAGE_CHUNK(cc) do {                                                  \
        int _st = (cc) % 3;                                                       \
        uint32_t _ab = sbase + (uint32_t)(_st * 2 * STG) * 4;                     \
        uint32_t _bb = _ab + (uint32_t)STG * 4;                                   \
        _Pragma("unroll")                                                         \
        for (int _j = 0; _j < 4; _j++) {                                          \
            int _r = row0 + _j * 32;                                              \
            uint32_t _o = (uint32_t)(_r * RST + seg * 4) * 4;                     \
            CP16(_ab + _o, Ap + (size_t)_j * 32 * 256 + (cc) * KCH);              \
            CP16(_bb + _o, Wp + (size_t)_j * 32 * 256 + (cc) * KCH);              \
        }                                                                         \
        CP_COMMIT();                                                              \
    } while (0)

    STAGE_CHUNK(0);
    STAGE_CHUNK(1);

    for (int c = 0; c < NCHUNK; c++) {
        if (c == NCHUNK - 1) CP_WAIT0(); else CP_WAIT1();
        __syncthreads();
        if (c + 2 < NCHUNK) STAGE_CHUNK(c + 2);

        const float* As = sm + (c % 3) * 2 * STG;
        const float* Bs = As + STG;
        #pragma unroll
        for (int kk = 0; kk < KCH; kk += 8) {
            uint32_t af[2][4];
            #pragma unroll
            for (int mi = 0; mi < 2; mi++) {
                int r = wm + mi * 16 + g;
                af[mi][0] = f2tf(As[r * RST + kk + tg]);
                af[mi][1] = f2tf(As[(r + 8) * RST + kk + tg]);
                af[mi][2] = f2tf(As[r * RST + kk + tg + 4]);
                af[mi][3] = f2tf(As[(r + 8) * RST + kk + tg + 4]);
            }
            uint32_t bf[8][2];
            #pragma unroll
            for (int ni = 0; ni < 8; ni++) {
                int n = wn + ni * 8 + g;
                bf[ni][0] = f2tf(Bs[n * RST + kk + tg]);
                bf[ni][1] = f2tf(Bs[n * RST + kk + tg + 4]);
            }
            #pragma unroll
            for (int mi = 0; mi < 2; mi++)
                #pragma unroll
                for (int ni = 0; ni < 8; ni++)
                    mma_tf32(acc[mi][ni], af[mi], bf[ni], acc[mi][ni]);
        }
        __syncthreads();
    }

    #pragma unroll
    for (int mi = 0; mi < 2; mi++) {
        #pragma unroll
        for (int ni = 0; ni < 8; ni++) {
            int row = m0 + wm + mi * 16 + g;
            int col = n0 + wn + ni * 8 + 2 * tg;
            float b0v = bias[col], b1v = bias[col + 1];
            *(float2*)&C[(size_t)row * Nout + col] =
                make_float2(acc[mi][ni][0] + b0v, acc[mi][ni][1] + b1v);
            *(float2*)&C[(size_t)(row + 8) * Nout + col] =
                make_float2(acc[mi][ni][2] + b0v, acc[mi][ni][3] + b1v);
        }
    }
}

// ---------------- fused attention: 3xTF32 S + 1xTF32 PV --------------------
// smem floats: 5*112*36 + 507 + 2*112 = 20891  (83564 bytes)
#define ATTN_SMEM_FLOATS (5 * MPAD * QST + TBL + 2 * MPAD)

__global__ __launch_bounds__(224, 2) void attn_kernel() {
    extern __shared__ float sm[];
    float* qhi = sm;                       // raw q during fill, then tf32-hi bits
    float* qlo = qhi + MPAD * QST;
    float* khi = qlo + MPAD * QST;
    float* klo = khi + MPAD * QST;
    float* vhi = klo + MPAD * QST;         // tf32(v)
    float* sbt = vhi + MPAD * QST;         // 507
    float* siq = sbt + TBL;                // 112 row scales (q, incl. logit scale)
    float* sik = siq + MPAD;               // 112 col scales (k)
    const uint32_t* qhiU = (const uint32_t*)qhi;
    const uint32_t* qloU = (const uint32_t*)qlo;
    const uint32_t* khiU = (const uint32_t*)khi;
    const uint32_t* kloU = (const uint32_t*)klo;
    const uint32_t* vhiU = (const uint32_t*)vhi;

    int bx = blockIdx.x;
    int w = bx >> 3, h = bx & 7;
    int tid = threadIdx.x;
    int warp = tid >> 5, lane = tid & 31;
    int g = lane >> 2, tg = lane & 3;

    // fill raw q/k/v into the *hi arrays (rows 98..111 zero)
    const float* base = g_qkv + (size_t)w * NTOK * 768 + h * HD;
    for (int e = tid; e < MPAD * 8; e += 224) {
        int n = e >> 3, d4 = (e & 7) * 4;
        float4 vq, vk, vv;
        if (n < NTOK) {
            const float* r = base + (size_t)n * 768;
            vq = *(const float4*)(r + d4);
            vk = *(const float4*)(r + 256 + d4);
            vv = *(const float4*)(r + 512 + d4);
        } else {
            vq = make_float4(0.f, 0.f, 0.f, 0.f); vk = vq; vv = vq;
        }
        *(float4*)&qhi[n * QST + d4] = vq;
        *(float4*)&khi[n * QST + d4] = vk;
        *(float4*)&vhi[n * QST + d4] = vv;
    }
    for (int e = tid; e < TBL; e += 224) sbt[e] = g_bt[e * NH + h];
    __syncthreads();

    // row norms -> scale factors
    float scale = g_scale[h];
    {
        int r = (tid < MPAD) ? tid : tid - MPAD;     // 224 threads = 112 q + 112 k
        const float* src = (tid < MPAD) ? &qhi[r * QST] : &khi[r * QST];
        float nn = 0.f;
        #pragma unroll
        for (int d4 = 0; d4 < HD; d4 += 4) {
            float4 v = *(const float4*)(src + d4);
            nn += v.x * v.x + v.y * v.y + v.z * v.z + v.w * v.w;
        }
        float inv = 1.f / fmaxf(sqrtf(nn), 1e-12f);
        if (tid < MPAD) siq[r] = scale * inv; else sik[r] = inv;
    }
    __syncthreads();

    // one-time hi/lo decomposition (scales folded into q, k pre-conversion)
    #define DECOMP4(HI, LO, off, sc) do {                                        \
        float4 _r = *(const float4*)&HI[off];                                    \
        uint4 _h, _l;                                                            \
        _h.x = f2tf(_r.x * sc); _l.x = f2tf(_r.x * sc - __uint_as_float(_h.x));  \
        _h.y = f2tf(_r.y * sc); _l.y = f2tf(_r.y * sc - __uint_as_float(_h.y));  \
        _h.z = f2tf(_r.z * sc); _l.z = f2tf(_r.z * sc - __uint_as_float(_h.z));  \
        _h.w = f2tf(_r.w * sc); _l.w = f2tf(_r.w * sc - __uint_as_float(_h.w));  \
        *(uint4*)&HI[off] = _h; *(uint4*)&LO[off] = _l;                          \
    } while (0)

    for (int e = tid; e < MPAD * 8; e += 224) {
        int n = e >> 3, d4 = (e & 7) * 4;
        int off = n * QST + d4;
        float fq = siq[n], fk = sik[n];
        DECOMP4(qhi, qlo, off, fq);
        DECOMP4(khi, klo, off, fk);
        // V: plain tf32 (1xTF32 PV)
        float4 _v = *(const float4*)&vhi[off];
        uint4 _vh = make_uint4(f2tf(_v.x), f2tf(_v.y), f2tf(_v.z), f2tf(_v.w));
        *(uint4*)&vhi[off] = _vh;
    }
    __syncthreads();

    // ---- S = qn @ kn^T via 3xTF32 mma; pure LDS + mma inner loop
    int mt = warp * 16;                      // 7 warps x m16 = 112 rows
    float acc[13][4];
    #pragma unroll
    for (int ni = 0; ni < 13; ni++)
        #pragma unroll
        for (int e = 0; e < 4; e++) acc[ni][e] = 0.f;

    #pragma unroll
    for (int ks = 0; ks < 4; ks++) {
        int kk = ks * 8;
        int o0 = (mt + g) * QST + kk + tg, o1 = (mt + g + 8) * QST + kk + tg;
        uint32_t ah[4] = {qhiU[o0], qhiU[o1], qhiU[o0 + 4], qhiU[o1 + 4]};
        uint32_t al[4] = {qloU[o0], qloU[o1], qloU[o0 + 4], qloU[o1 + 4]};
        #pragma unroll
        for (int ni = 0; ni < 13; ni++) {
            int ob = (ni * 8 + g) * QST + kk + tg;
            uint32_t bh[2] = {khiU[ob], khiU[ob + 4]};
            uint32_t bl[2] = {kloU[ob], kloU[ob + 4]};
            mma_tf32(acc[ni], ah, bh, acc[ni]);
            mma_tf32(acc[ni], ah, bl, acc[ni]);
            mma_tf32(acc[ni], al, bh, acc[ni]);
        }
    }

    // ---- in-register epilogue: + relative-position bias, pad mask
    int r0 = mt + g, r1 = r0 + 8;
    int di0 = 0, hi0 = 0, wi0 = 0, di1 = 0, hi1 = 0, wi1 = 0;
    if (r0 < NTOK) { di0 = r0 / 49; int rr = r0 % 49; hi0 = rr / 7; wi0 = rr % 7; }
    if (r1 < NTOK) { di1 = r1 / 49; int rr = r1 % 49; hi1 = rr / 7; wi1 = rr % 7; }
    #pragma unroll
    for (int ni = 0; ni < 13; ni++) {
        #pragma unroll
        for (int u = 0; u < 2; u++) {
            int c = ni * 8 + 2 * tg + u;
            if (c < NTOK) {
                int dj = c / 49, rj = c % 49, hj = rj / 7, wj = rj % 7;
                int base0 = -dj * 169 - hj * 13 - wj + 169 + 6 * 13 + 6;
                if (r0 < NTOK)
                    acc[ni][u] += sbt[di0 * 169 + hi0 * 13 + wi0 + base0];
                else acc[ni][u] = -1e30f;
                if (r1 < NTOK)
                    acc[ni][u + 2] += sbt[di1 * 169 + hi1 * 13 + wi1 + base0];
                else acc[ni][u + 2] = -1e30f;
            } else {
                acc[ni][u] = -1e30f;
                acc[ni][u + 2] = -1e30f;
            }
        }
    }

    // ---- softmax in registers (rows r0, r1 live in quad: shfl_xor 1,2)
    float m0 = -1e30f, m1 = -1e30f;
    #pragma unroll
    for (int ni = 0; ni < 13; ni++) {
        m0 = fmaxf(m0, fmaxf(acc[ni][0], acc[ni][1]));
        m1 = fmaxf(m1, fmaxf(acc[ni][2], acc[ni][3]));
    }
    m0 = fmaxf(m0, __shfl_xor_sync(~0u, m0, 1)); m0 = fmaxf(m0, __shfl_xor_sync(~0u, m0, 2));
    m1 = fmaxf(m1, __shfl_xor_sync(~0u, m1, 1)); m1 = fmaxf(m1, __shfl_xor_sync(~0u, m1, 2));
    float s0 = 0.f, s1 = 0.f;
    #pragma unroll
    for (int ni = 0; ni < 13; ni++) {
        acc[ni][0] = __expf(acc[ni][0] - m0); s0 += acc[ni][0];
        acc[ni][1] = __expf(acc[ni][1] - m0); s0 += acc[ni][1];
        acc[ni][2] = __expf(acc[ni][2] - m1); s1 += acc[ni][2];
        acc[ni][3] = __expf(acc[ni][3] - m1); s1 += acc[ni][3];
    }
    s0 += __shfl_xor_sync(~0u, s0, 1); s0 += __shfl_xor_sync(~0u, s0, 2);
    s1 += __shfl_xor_sync(~0u, s1, 1); s1 += __shfl_xor_sync(~0u, s1, 2);
    float i0 = 1.f / s0, i1 = 1.f / s1;
    #pragma unroll
    for (int ni = 0; ni < 13; ni++) {
        acc[ni][0] *= i0; acc[ni][1] *= i0;
        acc[ni][2] *= i1; acc[ni][3] *= i1;
    }

    // ---- O = P @ V via 1xTF32; P fragments built with quad shuffles
    float oacc[4][4];
    #pragma unroll
    for (int ni = 0; ni < 4; ni++)
        #pragma unroll
        for (int e = 0; e < 4; e++) oacc[ni][e] = 0.f;

    int qbase = lane & ~3;
    int L1 = qbase + (tg >> 1), L2 = L1 + 2;
    bool hi = (tg & 1);
    #pragma unroll
    for (int ks = 0; ks < 13; ks++) {
        int kk = ks * 8;
        float e0a = __shfl_sync(~0u, acc[ks][0], L1), e1a = __shfl_sync(~0u, acc[ks][1], L1);
        float e2a = __shfl_sync(~0u, acc[ks][2], L1), e3a = __shfl_sync(~0u, acc[ks][3], L1);
        float e0b = __shfl_sync(~0u, acc[ks][0], L2), e1b = __shfl_sync(~0u, acc[ks][1], L2);
        float e2b = __shfl_sync(~0u, acc[ks][2], L2), e3b = __shfl_sync(~0u, acc[ks][3], L2);
        float a0 = hi ? e1a : e0a;    // P[r0, kk+tg]
        float a1 = hi ? e3a : e2a;    // P[r1, kk+tg]
        float a2 = hi ? e1b : e0b;    // P[r0, kk+tg+4]
        float a3 = hi ? e3b : e2b;    // P[r1, kk+tg+4]
        uint32_t ah[4] = {f2tf(a0), f2tf(a1), f2tf(a2), f2tf(a3)};
        #pragma unroll
        for (int ni = 0; ni < 4; ni++) {
            int ob0 = (kk + tg) * QST + ni * 8 + g;
            int ob1 = (kk + tg + 4) * QST + ni * 8 + g;
            uint32_t bh[2] = {vhiU[ob0], vhiU[ob1]};
            mma_tf32(oacc[ni], ah, bh, oacc[ni]);
        }
    }
    float* outw = g_att + (size_t)w * NTOK * DIM + h * HD;
    #pragma unroll
    for (int ni = 0; ni < 4; ni++) {
        int c = ni * 8 + 2 * tg;
        if (r0 < NTOK)
            *(float2*)&outw[(size_t)r0 * DIM + c] = make_float2(oacc[ni][0], oacc[ni][1]);
        if (r1 < NTOK)
            *(float2*)&outw[(size_t)r1 * DIM + c] = make_float2(oacc[ni][2], oacc[ni][3]);
    }
}

// ---------------- launch ----------------
extern "C" void kernel_launch(void* const* d_in, const int* in_sizes, int n_in,
                              void* d_out, int out_size) {
    const float* x      = (const float*)d_in[0];
    const float* qkv_w  = (const float*)d_in[1];
    const float* q_bias = (const float*)d_in[2];
    const float* v_bias = (const float*)d_in[3];
    const float* ls     = (const float*)d_in[4];
    const float* cpb_w1 = (const float*)d_in[5];
    const float* cpb_b1 = (const float*)d_in[6];
    const float* cpb_w2 = (const float*)d_in[7];
    const float* proj_w = (const float*)d_in[8];
    const float* proj_b = (const float*)d_in[9];
    float* out = (float*)d_out;

    float *qkv, *att, *bias768;
    cudaGetSymbolAddress((void**)&qkv,     g_qkv);
    cudaGetSymbolAddress((void**)&att,     g_att);
    cudaGetSymbolAddress((void**)&bias768, g_bias768);

    setup_small<<<1, 768>>>(q_bias, v_bias, ls);
    cpb_kernel<<<TBL, 512>>>(cpb_w1, cpb_b1, cpb_w2);

    cudaFuncSetAttribute(gemm_tc, cudaFuncAttributeMaxDynamicSharedMemorySize, GEMM_SMEM);

    // QKV: [200704,256] @ qkv_w[768,256]^T + bias768
    gemm_tc<<<dim3(768 / 128, M_TOT / 128), 256, GEMM_SMEM>>>(x, qkv_w, bias768, qkv, 768);

    int smem_bytes = ATTN_SMEM_FLOATS * (int)sizeof(float);
    cudaFuncSetAttribute(attn_kernel, cudaFuncAttributeMaxDynamicSharedMemorySize, smem_bytes);
    attn_kernel<<<BW * NH, 224, smem_bytes>>>();

    // proj: [200704,256] @ proj_w[256,256]^T + proj_b
    gemm_tc<<<dim3(256 / 128, M_TOT / 128), 256, GEMM_SMEM>>>(att, proj_w, proj_b, out, 256);
}

// round 16
// speedup vs baseline: 2.0551x; 1.3622x over previous
#include <cuda_runtime.h>
#include <cuda_fp16.h>
#include <math.h>
#include <stdint.h>

#define DIM   256
#define NH    8
#define HD    32
#define NTOK  98
#define BW    2048
#define TBL   507                 // (2*2-1)*(2*7-1)*(2*7-1)
#define M_TOT (BW*NTOK)           // 200704
#define QSTF  36                  // fp32 staging row stride (floats)
#define HST   18                  // half2 row stride (u32) for q/k hi-lo
#define VST   60                  // vT row stride (u32)
#define MPAD  112                 // tokens padded to 7 x m16

// ---------------- device scratch (no allocations allowed) ----------------
__device__ float  g_qkv[(size_t)BW * NTOK * 3 * DIM];   // 616 MB fp32
__device__ __half g_att[(size_t)BW * NTOK * DIM];       // 103 MB half
__device__ __half g_xh[(size_t)M_TOT * DIM];            // 103 MB half
__device__ __half g_qkvwh[3 * DIM * DIM];
__device__ __half g_projwh[DIM * DIM];
__device__ float  g_bt[TBL * NH];                       // 16*sigmoid(cpb) table
__device__ float  g_bias768[3 * DIM];
__device__ float  g_scale[NH];

// ---------------- setup: fused bias + per-head logit scale ----------------
__global__ void setup_small(const float* __restrict__ qb,
                            const float* __restrict__ vb,
                            const float* __restrict__ ls) {
    int t = threadIdx.x;                       // 768 threads
    float b;
    if (t < 256)       b = qb[t];
    else if (t < 512)  b = 0.f;
    else               b = vb[t - 512];
    g_bias768[t] = b;
    if (t < NH) g_scale[t] = expf(fminf(ls[t], 4.6051701860f)); // log(100)
}

// ---------------- fp32 -> fp16 conversion (vectorized) ----------------
__global__ void to_half(const float* __restrict__ src, __half* __restrict__ dst,
                        int n4) {
    int i = blockIdx.x * 256 + threadIdx.x;
    if (i < n4) {
        float4 v = *(const float4*)(src + (size_t)i * 4);
        __half2 a = __floats2half2_rn(v.x, v.y);
        __half2 b = __floats2half2_rn(v.z, v.w);
        uint2 o = make_uint2(*(uint32_t*)&a, *(uint32_t*)&b);
        *(uint2*)(dst + (size_t)i * 4) = o;
    }
}

// ---------------- CPB MLP: table -> relu -> w2 -> 16*sigmoid ----------------
__global__ void cpb_kernel(const float* __restrict__ w1, const float* __restrict__ b1,
                           const float* __restrict__ w2) {
    __shared__ float hid[512];
    int t = blockIdx.x;                        // 0..506
    int a = t / 169, rem = t % 169, b = rem / 13, c = rem % 13;
    const float eps = 1e-6f;
    float ga = (float)(a - 1) / (2.f - (1.f - eps)) * 8.f;
    float gb = (float)(b - 6) / (7.f - (1.f - eps)) * 8.f;
    float gc = (float)(c - 6) / (7.f - (1.f - eps)) * 8.f;
    const float il8 = 1.f / log2f(8.f);
    ga = copysignf(log2f(fabsf(ga) + 1.f) * il8, ga);
    gb = copysignf(log2f(fabsf(gb) + 1.f) * il8, gb);
    gc = copysignf(log2f(fabsf(gc) + 1.f) * il8, gc);
    int j = threadIdx.x;                       // 512 threads
    float hv = ga * w1[j * 3 + 0] + gb * w1[j * 3 + 1] + gc * w1[j * 3 + 2] + b1[j];
    hid[j] = fmaxf(hv, 0.f);
    __syncthreads();
    if (j < NH) {
        float acc = 0.f;
        for (int q = 0; q < 512; q++) acc += hid[q] * w2[j * 512 + q];
        g_bt[t * NH + j] = 16.f / (1.f + expf(-acc));
    }
}

// ---------------- helpers ----------------
__device__ __forceinline__ uint32_t smem_u32(const void* p) {
    uint32_t a;
    asm("{ .reg .u64 t; cvta.to.shared.u64 t, %1; cvt.u32.u64 %0, t; }"
        : "=r"(a) : "l"(p));
    return a;
}

// m16n8k16 fp16 mma, fp32 accumulate.
__device__ __forceinline__ void mma_f16(float* d, const uint32_t* a,
                                        const uint32_t* b, const float* c) {
    asm volatile(
        "mma.sync.aligned.m16n8k16.row.col.f32.f16.f16.f32 "
        "{%0,%1,%2,%3}, {%4,%5,%6,%7}, {%8,%9}, {%10,%11,%12,%13};\n"
        : "=f"(d[0]), "=f"(d[1]), "=f"(d[2]), "=f"(d[3])
        : "r"(a[0]), "r"(a[1]), "r"(a[2]), "r"(a[3]),
          "r"(b[0]), "r"(b[1]),
          "f"(c[0]), "f"(c[1]), "f"(c[2]), "f"(c[3]));
}

__device__ __forceinline__ uint32_t pack_h2(float lo, float hi) {
    __half2 h = __floats2half2_rn(lo, hi);
    return *reinterpret_cast<uint32_t*>(&h);
}

#define CP16(dst, src) \
    asm volatile("cp.async.cg.shared.global [%0], [%1], 16;" :: "r"(dst), "l"(src))
#define CP_COMMIT() asm volatile("cp.async.commit_group;" ::: "memory")
#define CP_WAIT1()  asm volatile("cp.async.wait_group 1;" ::: "memory")
#define CP_WAIT0()  asm volatile("cp.async.wait_group 0;" ::: "memory")

// ---------------- fp16 mma GEMM, cp.async 3-stage ----------------
// C[M,Nout] = A[M,256] @ W[Nout,256]^T + bias (A, W half, K-major).
// CTA 128x128, K-chunk 32 halves (= 2 x k16 mma steps), 3 stages.
// m16n8k16 fragments (g=lane>>2, tg=lane&3), u32 = consecutive k-pair:
//   A: reg0=(g, pair tg) reg1=(g+8, pair tg) reg2=(g, pair tg+4) reg3=(g+8, pair tg+4)
//   B: reg0=(n=g, pair tg) reg1=(n=g, pair tg+4)
//   C: c0,c1=(g, 2tg..2tg+1)  c2,c3=(g+8, ...)
#define KCH    32
#define NCHUNK 8
#define RSTU   20                           // u32 per row per stage (16 data + 4 pad)
#define STGU   (128 * RSTU)                 // u32 per matrix stage
#define GEMM_SMEM (3 * 2 * STGU * 4)        // 61440 bytes

__global__ __launch_bounds__(256) void gemm_h(const __half* __restrict__ A,
                                              const __half* __restrict__ W,
                                              const float* __restrict__ bias,
                                              float* __restrict__ C, int Nout) {
    extern __shared__ float sm[];
    uint32_t sbase = smem_u32(sm);
    const uint32_t* smU = (const uint32_t*)sm;
    int tid = threadIdx.x;
    int wid = tid >> 5, lane = tid & 31;
    int g = lane >> 2, tg = lane & 3;
    int m0 = blockIdx.y * 128, n0 = blockIdx.x * 128;
    int wm = (wid & 3) * 32, wn = (wid >> 2) * 64;

    float acc[2][8][4] = {};

    int row0 = tid >> 2, seg = tid & 3;      // rows row0, row0+64; 16B segment
    const __half* Ap = A + (size_t)(m0 + row0) * 256 + seg * 8;
    const __half* Wp = W + (size_t)(n0 + row0) * 256 + seg * 8;

    #define STAGE_CHUNK(cc) do {                                                  \
        int _st = (cc) % 3;                                                       \
        uint32_t _ab = sbase + (uint32_t)(_st * 2 * STGU) * 4;                    \
        uint32_t _bb = _ab + (uint32_t)STGU * 4;                                  \
        _Pragma("unroll")                                                         \
        for (int _j = 0; _j < 2; _j++) {                                          \
            int _r = row0 + _j * 64;                                              \
            uint32_t _o = (uint32_t)(_r * RSTU + seg * 4) * 4;                    \
            CP16(_ab + _o, Ap + (size_t)_j * 64 * 256 + (cc) * KCH);              \
            CP16(_bb + _o, Wp + (size_t)_j * 64 * 256 + (cc) * KCH);              \
        }                                                                         \
        CP_COMMIT();                                                              \
    } while (0)

    STAGE_CHUNK(0);
    STAGE_CHUNK(1);

    for (int c = 0; c < NCHUNK; c++) {
        if (c == NCHUNK - 1) CP_WAIT0(); else CP_WAIT1();
        __syncthreads();
        if (c + 2 < NCHUNK) STAGE_CHUNK(c + 2);

        const uint32_t* As = smU + (c % 3) * 2 * STGU;
        const uint32_t* Bs = As + STGU;
        #pragma unroll
        for (int s = 0; s < 2; s++) {        // two k16 steps per chunk
            uint32_t af[2][4];
            #pragma unroll
            for (int mi = 0; mi < 2; mi++) {
                int r = wm + mi * 16 + g;
                int b0 = r * RSTU + s * 8, b1 = (r + 8) * RSTU + s * 8;
                af[mi][0] = As[b0 + tg];
                af[mi][1] = As[b1 + tg];
                af[mi][2] = As[b0 + tg + 4];
                af[mi][3] = As[b1 + tg + 4];
            }
            uint32_t bf[8][2];
            #pragma unroll
            for (int ni = 0; ni < 8; ni++) {
                int n = wn + ni * 8 + g;
                bf[ni][0] = Bs[n * RSTU + s * 8 + tg];
                bf[ni][1] = Bs[n * RSTU + s * 8 + tg + 4];
            }
            #pragma unroll
            for (int mi = 0; mi < 2; mi++)
                #pragma unroll
                for (int ni = 0; ni < 8; ni++)
                    mma_f16(acc[mi][ni], af[mi], bf[ni], acc[mi][ni]);
        }
        __syncthreads();
    }

    #pragma unroll
    for (int mi = 0; mi < 2; mi++) {
        #pragma unroll
        for (int ni = 0; ni < 8; ni++) {
            int row = m0 + wm + mi * 16 + g;
            int col = n0 + wn + ni * 8 + 2 * tg;
            float b0v = bias[col], b1v = bias[col + 1];
            *(float2*)&C[(size_t)row * Nout + col] =
                make_float2(acc[mi][ni][0] + b0v, acc[mi][ni][1] + b1v);
            *(float2*)&C[(size_t)(row + 8) * Nout + col] =
                make_float2(acc[mi][ni][2] + b0v, acc[mi][ni][3] + b1v);
        }
    }
}

// ---------------- fused attention: 3x-fp16 S + 1x-fp16 PV ------------------
// smem floats: 2*4032 (fp32 staging) + 4*2016 (q/k hi-lo u32) + 1920 (vT)
//              + 507 + 224 = 18779 floats = 75116 bytes
#define ATTN_SMEM_FLOATS (2 * MPAD * QSTF + 4 * MPAD * HST + 32 * VST + TBL + 2 * MPAD)

__global__ __launch_bounds__(224, 2) void attn_kernel() {
    extern __shared__ float sm[];
    float*    sqf = sm;                           // [112][36] fp32 staging q
    float*    skf = sqf + MPAD * QSTF;            // [112][36] fp32 staging k
    uint32_t* qh  = (uint32_t*)(skf + MPAD * QSTF);   // [112][18] half2
    uint32_t* ql  = qh + MPAD * HST;
    uint32_t* kh  = ql + MPAD * HST;
    uint32_t* kl  = kh + MPAD * HST;
    uint32_t* vT  = kl + MPAD * HST;              // [32][60] half2 (V transposed)
    float*    sbt = (float*)(vT + 32 * VST);      // 507
    float*    siq = sbt + TBL;                    // 112 q scales (incl logit scale)
    float*    sik = siq + MPAD;                   // 112 k scales
    __half*   vTh = (__half*)vT;                  // u16 view, row stride 120

    int bx = blockIdx.x;
    int w = bx >> 3, h = bx & 7;
    int tid = threadIdx.x;
    int warp = tid >> 5, lane = tid & 31;
    int g = lane >> 2, tg = lane & 3;

    // fill: q,k raw fp32 to staging; v converted+transposed into vT
    const float* base = g_qkv + (size_t)w * NTOK * 768 + h * HD;
    for (int e = tid; e < MPAD * 8; e += 224) {
        int n = e >> 3, d4 = (e & 7) * 4;
        float4 vq, vk, vv;
        if (n < NTOK) {
            const float* r = base + (size_t)n * 768;
            vq = *(const float4*)(r + d4);
            vk = *(const float4*)(r + 256 + d4);
            vv = *(const float4*)(r + 512 + d4);
        } else {
            vq = make_float4(0.f, 0.f, 0.f, 0.f); vk = vq; vv = vq;
        }
        *(float4*)&sqf[n * QSTF + d4] = vq;
        *(float4*)&skf[n * QSTF + d4] = vk;
        vTh[(d4 + 0) * 120 + n] = __float2half_rn(vv.x);
        vTh[(d4 + 1) * 120 + n] = __float2half_rn(vv.y);
        vTh[(d4 + 2) * 120 + n] = __float2half_rn(vv.z);
        vTh[(d4 + 3) * 120 + n] = __float2half_rn(vv.w);
    }
    for (int e = tid; e < TBL; e += 224) sbt[e] = g_bt[e * NH + h];
    __syncthreads();

    // row norms -> scale factors
    float scale = g_scale[h];
    {
        int r = (tid < MPAD) ? tid : tid - MPAD;
        const float* src = (tid < MPAD) ? &sqf[r * QSTF] : &skf[r * QSTF];
        float nn = 0.f;
        #pragma unroll
        for (int d4 = 0; d4 < HD; d4 += 4) {
            float4 v = *(const float4*)(src + d4);
            nn += v.x * v.x + v.y * v.y + v.z * v.z + v.w * v.w;
        }
        float inv = 1.f / fmaxf(sqrtf(nn), 1e-12f);
        if (tid < MPAD) siq[r] = scale * inv; else sik[r] = inv;
    }
    __syncthreads();

    // one-time fp16 hi/lo decomposition with scales folded in
    for (int e = tid; e < MPAD * 8; e += 224) {
        int n = e >> 3, d4 = (e & 7) * 4;
        float fq = siq[n], fk = sik[n];
        float4 q4 = *(const float4*)&sqf[n * QSTF + d4];
        float4 k4 = *(const float4*)&skf[n * QSTF + d4];
        float qv[4] = {q4.x * fq, q4.y * fq, q4.z * fq, q4.w * fq};
        float kv[4] = {k4.x * fk, k4.y * fk, k4.z * fk, k4.w * fk};
        float qhf[4], khf[4];
        #pragma unroll
        for (int u = 0; u < 4; u++) {
            qhf[u] = __half2float(__float2half_rn(qv[u]));
            khf[u] = __half2float(__float2half_rn(kv[u]));
        }
        int o = n * HST + d4 / 2;
        qh[o]     = pack_h2(qhf[0], qhf[1]);
        qh[o + 1] = pack_h2(qhf[2], qhf[3]);
        ql[o]     = pack_h2(qv[0] - qhf[0], qv[1] - qhf[1]);
        ql[o + 1] = pack_h2(qv[2] - qhf[2], qv[3] - qhf[3]);
        kh[o]     = pack_h2(khf[0], khf[1]);
        kh[o + 1] = pack_h2(khf[2], khf[3]);
        kl[o]     = pack_h2(kv[0] - khf[0], kv[1] - khf[1]);
        kl[o + 1] = pack_h2(kv[2] - khf[2], kv[3] - khf[3]);
    }
    __syncthreads();

    // ---- S = qs @ ks^T via 3x-fp16 mma (k32 = 2 x k16 steps, 14 n8 tiles)
    int mt = warp * 16;                      // 7 warps x m16 = 112 rows
    float acc[14][4];
    #pragma unroll
    for (int ni = 0; ni < 14; ni++)
        #pragma unroll
        for (int e = 0; e < 4; e++) acc[ni][e] = 0.f;

    #pragma unroll
    for (int ks = 0; ks < 2; ks++) {
        int o0 = (mt + g) * HST + ks * 8, o1 = (mt + g + 8) * HST + ks * 8;
        uint32_t ah[4] = {qh[o0 + tg], qh[o1 + tg], qh[o0 + tg + 4], qh[o1 + tg + 4]};
        uint32_t al[4] = {ql[o0 + tg], ql[o1 + tg], ql[o0 + tg + 4], ql[o1 + tg + 4]};
        #pragma unroll
        for (int ni = 0; ni < 14; ni++) {
            int ob = (ni * 8 + g) * HST + ks * 8;
            uint32_t bh[2] = {kh[ob + tg], kh[ob + tg + 4]};
            uint32_t bl[2] = {kl[ob + tg], kl[ob + tg + 4]};
            mma_f16(acc[ni], ah, bh, acc[ni]);
            mma_f16(acc[ni], ah, bl, acc[ni]);
            mma_f16(acc[ni], al, bh, acc[ni]);
        }
    }

    // ---- in-register epilogue: + relative-position bias, pad mask
    int r0 = mt + g, r1 = r0 + 8;
    int di0 = 0, hi0 = 0, wi0 = 0, di1 = 0, hi1 = 0, wi1 = 0;
    if (r0 < NTOK) { di0 = r0 / 49; int rr = r0 % 49; hi0 = rr / 7; wi0 = rr % 7; }
    if (r1 < NTOK) { di1 = r1 / 49; int rr = r1 % 49; hi1 = rr / 7; wi1 = rr % 7; }
    #pragma unroll
    for (int ni = 0; ni < 14; ni++) {
        #pragma unroll
        for (int u = 0; u < 2; u++) {
            int c = ni * 8 + 2 * tg + u;
            if (c < NTOK) {
                int dj = c / 49, rj = c % 49, hj = rj / 7, wj = rj % 7;
                int base0 = -dj * 169 - hj * 13 - wj + 169 + 6 * 13 + 6;
                if (r0 < NTOK)
                    acc[ni][u] += sbt[di0 * 169 + hi0 * 13 + wi0 + base0];
                else acc[ni][u] = -1e30f;
                if (r1 < NTOK)
                    acc[ni][u + 2] += sbt[di1 * 169 + hi1 * 13 + wi1 + base0];
                else acc[ni][u + 2] = -1e30f;
            } else {
                acc[ni][u] = -1e30f;
                acc[ni][u + 2] = -1e30f;
            }
        }
    }

    // ---- softmax in registers (rows r0, r1 live in quad: shfl_xor 1,2)
    float m0 = -1e30f, m1 = -1e30f;
    #pragma unroll
    for (int ni = 0; ni < 14; ni++) {
        m0 = fmaxf(m0, fmaxf(acc[ni][0], acc[ni][1]));
        m1 = fmaxf(m1, fmaxf(acc[ni][2], acc[ni][3]));
    }
    m0 = fmaxf(m0, __shfl_xor_sync(~0u, m0, 1)); m0 = fmaxf(m0, __shfl_xor_sync(~0u, m0, 2));
    m1 = fmaxf(m1, __shfl_xor_sync(~0u, m1, 1)); m1 = fmaxf(m1, __shfl_xor_sync(~0u, m1, 2));
    float s0 = 0.f, s1 = 0.f;
    #pragma unroll
    for (int ni = 0; ni < 14; ni++) {
        acc[ni][0] = __expf(acc[ni][0] - m0); s0 += acc[ni][0];
        acc[ni][1] = __expf(acc[ni][1] - m0); s0 += acc[ni][1];
        acc[ni][2] = __expf(acc[ni][2] - m1); s1 += acc[ni][2];
        acc[ni][3] = __expf(acc[ni][3] - m1); s1 += acc[ni][3];
    }
    s0 += __shfl_xor_sync(~0u, s0, 1); s0 += __shfl_xor_sync(~0u, s0, 2);
    s1 += __shfl_xor_sync(~0u, s1, 1); s1 += __shfl_xor_sync(~0u, s1, 2);
    float i0 = 1.f / s0, i1 = 1.f / s1;
    #pragma unroll
    for (int ni = 0; ni < 14; ni++) {
        acc[ni][0] *= i0; acc[ni][1] *= i0;
        acc[ni][2] *= i1; acc[ni][3] *= i1;
    }

    // ---- O = P @ V via 1x-fp16 (7 k16 chunks); P fragments = acc regs directly
    float oacc[4][4];
    #pragma unroll
    for (int ni = 0; ni < 4; ni++)
        #pragma unroll
        for (int e = 0; e < 4; e++) oacc[ni][e] = 0.f;

    #pragma unroll
    for (int kc = 0; kc < 7; kc++) {
        uint32_t pa[4];
        pa[0] = pack_h2(acc[2 * kc][0],     acc[2 * kc][1]);      // row r0, k-pair 2tg
        pa[1] = pack_h2(acc[2 * kc][2],     acc[2 * kc][3]);      // row r1
        pa[2] = pack_h2(acc[2 * kc + 1][0], acc[2 * kc + 1][1]);  // row r0, k-pair 2tg+8
        pa[3] = pack_h2(acc[2 * kc + 1][2], acc[2 * kc + 1][3]);  // row r1
        #pragma unroll
        for (int ni = 0; ni < 4; ni++) {
            int vb = (ni * 8 + g) * VST + kc * 8;
            uint32_t bh[2] = {vT[vb + tg], vT[vb + tg + 4]};
            mma_f16(oacc[ni], pa, bh, oacc[ni]);
        }
    }
    __half* outw = g_att + (size_t)w * NTOK * DIM + h * HD;
    #pragma unroll
    for (int ni = 0; ni < 4; ni++) {
        int c = ni * 8 + 2 * tg;
        if (r0 < NTOK)
            *(uint32_t*)&outw[(size_t)r0 * DIM + c] = pack_h2(oacc[ni][0], oacc[ni][1]);
        if (r1 < NTOK)
            *(uint32_t*)&outw[(size_t)r1 * DIM + c] = pack_h2(oacc[ni][2], oacc[ni][3]);
    }
}

// ---------------- launch ----------------
extern "C" void kernel_launch(void* const* d_in, const int* in_sizes, int n_in,
                              void* d_out, int out_size) {
    const float* x      = (const float*)d_in[0];
    const float* qkv_w  = (const float*)d_in[1];
    const float* q_bias = (const float*)d_in[2];
    const float* v_bias = (const float*)d_in[3];
    const float* ls     = (const float*)d_in[4];
    const float* cpb_w1 = (const float*)d_in[5];
    const float* cpb_b1 = (const float*)d_in[6];
    const float* cpb_w2 = (const float*)d_in[7];
    const float* proj_w = (const float*)d_in[8];
    const float* proj_b = (const float*)d_in[9];
    float* out = (float*)d_out;

    float *qkv, *bias768;
    __half *xh, *qkvwh, *projwh, *att;
    cudaGetSymbolAddress((void**)&qkv,     g_qkv);
    cudaGetSymbolAddress((void**)&att,     g_att);
    cudaGetSymbolAddress((void**)&xh,      g_xh);
    cudaGetSymbolAddress((void**)&qkvwh,   g_qkvwh);
    cudaGetSymbolAddress((void**)&projwh,  g_projwh);
    cudaGetSymbolAddress((void**)&bias768, g_bias768);

    setup_small<<<1, 768>>>(q_bias, v_bias, ls);
    cpb_kernel<<<TBL, 512>>>(cpb_w1, cpb_b1, cpb_w2);

    // fp32 -> fp16 pre-conversion
    to_half<<<(M_TOT * DIM / 4 + 255) / 256, 256>>>(x, xh, M_TOT * DIM / 4);
    to_half<<<(3 * DIM * DIM / 4 + 255) / 256, 256>>>(qkv_w, qkvwh, 3 * DIM * DIM / 4);
    to_half<<<(DIM * DIM / 4 + 255) / 256, 256>>>(proj_w, projwh, DIM * DIM / 4);

    cudaFuncSetAttribute(gemm_h, cudaFuncAttributeMaxDynamicSharedMemorySize, GEMM_SMEM);

    // QKV: [200704,256]h @ qkv_w[768,256]h^T + bias768 -> fp32 qkv
    gemm_h<<<dim3(768 / 128, M_TOT / 128), 256, GEMM_SMEM>>>(xh, qkvwh, bias768, qkv, 768);

    int smem_bytes = ATTN_SMEM_FLOATS * (int)sizeof(float);
    cudaFuncSetAttribute(attn_kernel, cudaFuncAttributeMaxDynamicSharedMemorySize, smem_bytes);
    attn_kernel<<<BW * NH, 224, smem_bytes>>>();

    // proj: att[200704,256]h @ proj_w[256,256]h^T + proj_b -> fp32 out
    gemm_h<<<dim3(256 / 128, M_TOT / 128), 256, GEMM_SMEM>>>(att, projwh, proj_b, out, 256);
}